// round 1
// baseline (speedup 1.0000x reference)
#include <cuda_runtime.h>
#include <cuda_bf16.h>

#define N_MAX 100000
#define D 128

// Scratch (device globals: no allocation allowed in kernel_launch)
__device__ float g_h1[(size_t)N_MAX * D];
__device__ float g_agg1[(size_t)N_MAX * D];
__device__ float g_h2[(size_t)N_MAX * D];
__device__ float g_agg2[(size_t)N_MAX * D];
__device__ float g_dinv[N_MAX];
__device__ int   g_deg[N_MAX];

// ---------------- degree / norm ----------------

__global__ void zero_deg_kernel(int n) {
    int i = blockIdx.x * blockDim.x + threadIdx.x;
    if (i < n) g_deg[i] = 0;
}

__global__ void count_deg_kernel(const int* __restrict__ dst, int E) {
    int e = blockIdx.x * blockDim.x + threadIdx.x;
    if (e < E) atomicAdd(&g_deg[dst[e]], 1);
}

__global__ void dinv_kernel(int n) {
    int i = blockIdx.x * blockDim.x + threadIdx.x;
    if (i < n) g_dinv[i] = rsqrtf((float)g_deg[i] + 1.0f);  // +1 self loop
}

// ---------------- GEMM: out[n, NCOL] = f(in[n,128]) @ W[128, NCOL] (+ bout) ----
// INMODE: 0 = plain, 1 = relu(in + bin[k]), 2 = in + bin[k]

template<int NCOL, int TN, int INMODE, bool OUTBIAS>
__global__ void gemm_kernel(const float* __restrict__ in,
                            const float* __restrict__ W,
                            const float* __restrict__ bin,
                            const float* __restrict__ bout,
                            float* __restrict__ out, int n) {
    constexpr int KT    = 32;
    constexpr int BROWS = 64;
    constexpr int CG    = NCOL / TN;    // column groups
    constexpr int RG    = 256 / CG;     // row groups
    constexpr int TM    = BROWS / RG;   // rows per thread

    __shared__ float ws[KT][NCOL];
    __shared__ float xs[BROWS][KT];

    const int tid  = threadIdx.x;
    const int tcol = tid % CG;
    const int trow = tid / CG;
    const int row0 = blockIdx.x * BROWS;

    float acc[TM][TN];
#pragma unroll
    for (int i = 0; i < TM; i++)
#pragma unroll
        for (int j = 0; j < TN; j++) acc[i][j] = 0.0f;

    for (int k0 = 0; k0 < 128; k0 += KT) {
        // W tile: [KT, NCOL]
        for (int i = tid; i < KT * NCOL; i += 256) {
            int kk = i / NCOL, c = i % NCOL;
            ws[kk][c] = W[(size_t)(k0 + kk) * NCOL + c];
        }
        // X tile: [BROWS, KT] with fused input transform
        for (int i = tid; i < BROWS * KT; i += 256) {
            int r = i / KT, kk = i % KT;
            int row = row0 + r;
            float v = 0.0f;
            if (row < n) {
                v = in[(size_t)row * 128 + k0 + kk];
                if (INMODE == 1) { v += bin[k0 + kk]; v = fmaxf(v, 0.0f); }
                else if (INMODE == 2) { v += bin[k0 + kk]; }
            }
            xs[r][kk] = v;
        }
        __syncthreads();

#pragma unroll
        for (int kk = 0; kk < KT; kk++) {
            float wv[TN], xv[TM];
#pragma unroll
            for (int j = 0; j < TN; j++) wv[j] = ws[kk][tcol * TN + j];
#pragma unroll
            for (int i = 0; i < TM; i++) xv[i] = xs[trow * TM + i][kk];
#pragma unroll
            for (int i = 0; i < TM; i++)
#pragma unroll
                for (int j = 0; j < TN; j++) acc[i][j] += xv[i] * wv[j];
        }
        __syncthreads();
    }

#pragma unroll
    for (int i = 0; i < TM; i++) {
        int row = row0 + trow * TM + i;
        if (row < n) {
#pragma unroll
            for (int j = 0; j < TN; j++) {
                float v = acc[i][j];
                if (OUTBIAS) v += bout[tcol * TN + j];
                out[(size_t)row * NCOL + tcol * TN + j] = v;
            }
        }
    }
}

// ---------------- self-loop prefill: out[i,:] = h[i,:] * dinv[i]^2 ----------

__global__ void selfloop_prefill_kernel(const float* __restrict__ h,
                                        float* __restrict__ out, int n) {
    long idx = (long)blockIdx.x * blockDim.x + threadIdx.x;   // one float4 per thread
    long total = (long)n * (D / 4);
    if (idx >= total) return;
    int node = (int)(idx >> 5);            // 32 float4 per row
    float di = g_dinv[node];
    float w = di * di;
    float4 v = ((const float4*)h)[idx];
    v.x *= w; v.y *= w; v.z *= w; v.w *= w;
    ((float4*)out)[idx] = v;
}

// ---------------- edge aggregation: out[dst] += h[src] * dinv[src]*dinv[dst] --

__global__ void edge_agg_kernel(const int* __restrict__ src,
                                const int* __restrict__ dst,
                                const float* __restrict__ h,
                                float* __restrict__ out, int E) {
    int warps_per_block = blockDim.x >> 5;
    int e = blockIdx.x * warps_per_block + (threadIdx.x >> 5);
    if (e >= E) return;
    int s = __ldg(&src[e]);
    int d = __ldg(&dst[e]);
    float w = g_dinv[s] * g_dinv[d];
    int lane = threadIdx.x & 31;
    float4 hv = ((const float4*)(h + (size_t)s * D))[lane];
    float* o = out + (size_t)d * D + lane * 4;
    atomicAdd(o + 0, hv.x * w);
    atomicAdd(o + 1, hv.y * w);
    atomicAdd(o + 2, hv.z * w);
    atomicAdd(o + 3, hv.w * w);
}

// ---------------- launch ----------------

extern "C" void kernel_launch(void* const* d_in, const int* in_sizes, int n_in,
                              void* d_out, int out_size) {
    const float* x    = (const float*)d_in[0];
    const int*   ei   = (const int*)  d_in[1];
    const float* W1   = (const float*)d_in[2];
    const float* b1   = (const float*)d_in[3];
    const float* W2   = (const float*)d_in[4];
    const float* b2   = (const float*)d_in[5];
    const float* Wout = (const float*)d_in[6];
    const float* bout = (const float*)d_in[7];

    const int n = in_sizes[0] / D;
    const int E = in_sizes[1] / 2;
    const int* src = ei;
    const int* dst = ei + E;

    float *h1, *agg1, *h2, *agg2;
    cudaGetSymbolAddress((void**)&h1,   g_h1);
    cudaGetSymbolAddress((void**)&agg1, g_agg1);
    cudaGetSymbolAddress((void**)&h2,   g_h2);
    cudaGetSymbolAddress((void**)&agg2, g_agg2);

    // degrees + normalization
    zero_deg_kernel<<<(n + 255) / 256, 256>>>(n);
    count_deg_kernel<<<(E + 255) / 256, 256>>>(dst, E);
    dinv_kernel<<<(n + 255) / 256, 256>>>(n);

    const int gemm_blocks = (n + 63) / 64;
    const long pf_threads = (long)n * (D / 4);
    const int pf_blocks = (int)((pf_threads + 255) / 256);
    const int edge_blocks = (E + 7) / 8;

    // layer 1
    gemm_kernel<128, 4, 0, false><<<gemm_blocks, 256>>>(x, W1, nullptr, nullptr, h1, n);
    selfloop_prefill_kernel<<<pf_blocks, 256>>>(h1, agg1, n);
    edge_agg_kernel<<<edge_blocks, 256>>>(src, dst, h1, agg1, E);

    // layer 2 (relu(agg1 + b1) fused into GEMM input)
    gemm_kernel<128, 4, 1, false><<<gemm_blocks, 256>>>(agg1, W2, b1, nullptr, h2, n);
    selfloop_prefill_kernel<<<pf_blocks, 256>>>(h2, agg2, n);
    edge_agg_kernel<<<edge_blocks, 256>>>(src, dst, h2, agg2, E);

    // output layer: (agg2 + b2) @ Wout + bout
    gemm_kernel<40, 5, 2, true><<<gemm_blocks, 256>>>(agg2, Wout, b2, bout,
                                                      (float*)d_out, n);
}

// round 3
// speedup vs baseline: 2.3929x; 2.3929x over previous
#include <cuda_runtime.h>
#include <cuda_bf16.h>

#define N_MAX 100000
#define E_MAX 1700000
#define D 128

// Scratch (device globals: no allocation allowed in kernel_launch)
__device__ float  g_h1[(size_t)N_MAX * D];
__device__ float  g_agg1[(size_t)N_MAX * D];
__device__ float  g_h2[(size_t)N_MAX * D];
__device__ float  g_agg2[(size_t)N_MAX * D];
__device__ float  g_dinv[N_MAX];
__device__ int    g_deg[N_MAX];
__device__ int    g_fill[N_MAX];
__device__ int    g_rowptr[N_MAX + 1];
__device__ float2 g_edges[E_MAX];   // .x = src (bits), .y = weight

// ---------------- degree / norm ----------------

__global__ void zero_kernel(int n) {
    int i = blockIdx.x * blockDim.x + threadIdx.x;
    if (i < n) { g_deg[i] = 0; g_fill[i] = 0; }
}

__global__ void count_deg_kernel(const int* __restrict__ dst, int E) {
    int e = blockIdx.x * blockDim.x + threadIdx.x;
    if (e < E) atomicAdd(&g_deg[dst[e]], 1);
}

__global__ void dinv_kernel(int n) {
    int i = blockIdx.x * blockDim.x + threadIdx.x;
    if (i < n) g_dinv[i] = rsqrtf((float)g_deg[i] + 1.0f);  // +1 self loop
}

// ---------------- exclusive scan of g_deg -> g_rowptr (single block) --------

__global__ void scan_kernel(int n) {
    __shared__ int warp_tot[32];
    __shared__ int warp_off[32];
    __shared__ int carry_sh;
    const int tid  = threadIdx.x;
    const int lane = tid & 31;
    const int wid  = tid >> 5;
    if (tid == 0) carry_sh = 0;
    __syncthreads();

    const int nchunks = (n + 4095) / 4096;
    for (int c = 0; c < nchunks; c++) {
        int base = c * 4096 + tid * 4;
        int v[4];
#pragma unroll
        for (int j = 0; j < 4; j++) {
            int i = base + j;
            v[j] = (i < n) ? g_deg[i] : 0;
        }
        int s = v[0] + v[1] + v[2] + v[3];
        // warp-inclusive scan of s
        int incl = s;
#pragma unroll
        for (int off = 1; off < 32; off <<= 1) {
            int t = __shfl_up_sync(0xFFFFFFFFu, incl, off);
            if (lane >= off) incl += t;
        }
        if (lane == 31) warp_tot[wid] = incl;
        __syncthreads();
        if (wid == 0) {
            int t = warp_tot[lane];
            int ti = t;
#pragma unroll
            for (int off = 1; off < 32; off <<= 1) {
                int u = __shfl_up_sync(0xFFFFFFFFu, ti, off);
                if (lane >= off) ti += u;
            }
            warp_off[lane] = ti - t;           // exclusive warp offsets
            if (lane == 31) warp_tot[0] = ti;  // chunk total
        }
        __syncthreads();
        int carry = carry_sh;
        int excl = carry + warp_off[wid] + (incl - s);
#pragma unroll
        for (int j = 0; j < 4; j++) {
            int i = base + j;
            if (i < n) g_rowptr[i] = excl;
            excl += v[j];
        }
        int chunk_total = warp_tot[0];
        __syncthreads();
        if (tid == 0) carry_sh = carry + chunk_total;
        __syncthreads();
    }
    if (tid == 0) g_rowptr[n] = carry_sh;
}

// ---------------- scatter edges into CSR order with precomputed weight ------

__global__ void scatter_kernel(const int* __restrict__ src,
                               const int* __restrict__ dst, int E) {
    int e = blockIdx.x * blockDim.x + threadIdx.x;
    if (e >= E) return;
    int s = src[e];
    int d = dst[e];
    int pos = g_rowptr[d] + atomicAdd(&g_fill[d], 1);
    g_edges[pos] = make_float2(__int_as_float(s), g_dinv[s] * g_dinv[d]);
}

// ---------------- GEMM: out[n, NCOL] = f(in[n,128]) @ W[128, NCOL] (+ bout) ----
// INMODE: 0 = plain, 1 = relu(in + bin[k]), 2 = in + bin[k]

template<int NCOL, int TN, int INMODE, bool OUTBIAS>
__global__ void gemm_kernel(const float* __restrict__ in,
                            const float* __restrict__ W,
                            const float* __restrict__ bin,
                            const float* __restrict__ bout,
                            float* __restrict__ out, int n) {
    constexpr int KT    = 32;
    constexpr int BROWS = 64;
    constexpr int CG    = NCOL / TN;    // column groups
    constexpr int RG    = 256 / CG;     // row groups
    constexpr int TM    = BROWS / RG;   // rows per thread

    __shared__ float ws[KT][NCOL];
    __shared__ float xs[BROWS][KT];

    const int tid  = threadIdx.x;
    const int tcol = tid % CG;
    const int trow = tid / CG;
    const int row0 = blockIdx.x * BROWS;

    float acc[TM][TN];
#pragma unroll
    for (int i = 0; i < TM; i++)
#pragma unroll
        for (int j = 0; j < TN; j++) acc[i][j] = 0.0f;

    for (int k0 = 0; k0 < 128; k0 += KT) {
        for (int i = tid; i < KT * NCOL; i += 256) {
            int kk = i / NCOL, c = i % NCOL;
            ws[kk][c] = W[(size_t)(k0 + kk) * NCOL + c];
        }
        for (int i = tid; i < BROWS * KT; i += 256) {
            int r = i / KT, kk = i % KT;
            int row = row0 + r;
            float v = 0.0f;
            if (row < n) {
                v = in[(size_t)row * 128 + k0 + kk];
                if (INMODE == 1) { v += bin[k0 + kk]; v = fmaxf(v, 0.0f); }
                else if (INMODE == 2) { v += bin[k0 + kk]; }
            }
            xs[r][kk] = v;
        }
        __syncthreads();

#pragma unroll
        for (int kk = 0; kk < KT; kk++) {
            float wv[TN], xv[TM];
#pragma unroll
            for (int j = 0; j < TN; j++) wv[j] = ws[kk][tcol * TN + j];
#pragma unroll
            for (int i = 0; i < TM; i++) xv[i] = xs[trow * TM + i][kk];
#pragma unroll
            for (int i = 0; i < TM; i++)
#pragma unroll
                for (int j = 0; j < TN; j++) acc[i][j] += xv[i] * wv[j];
        }
        __syncthreads();
    }

#pragma unroll
    for (int i = 0; i < TM; i++) {
        int row = row0 + trow * TM + i;
        if (row < n) {
#pragma unroll
            for (int j = 0; j < TN; j++) {
                float v = acc[i][j];
                if (OUTBIAS) v += bout[tcol * TN + j];
                out[(size_t)row * NCOL + tcol * TN + j] = v;
            }
        }
    }
}

// ---------------- aggregation: one warp per node, no float atomics ----------
// out[node] = h[node]*dinv[node]^2 + sum_{e in CSR[node]} h[src_e]*w_e

__global__ void agg_kernel(const float* __restrict__ h,
                           float* __restrict__ out, int n) {
    int warp = (blockIdx.x * blockDim.x + threadIdx.x) >> 5;
    if (warp >= n) return;
    const int node = warp;
    const int lane = threadIdx.x & 31;

    const float4* hb = (const float4*)h;
    float di = g_dinv[node];
    float w0 = di * di;
    float4 acc = hb[(size_t)node * 32 + lane];
    acc.x *= w0; acc.y *= w0; acc.z *= w0; acc.w *= w0;

    int e   = g_rowptr[node];
    int end = g_rowptr[node + 1];

    for (; e + 4 <= end; e += 4) {
        float2 e0 = g_edges[e + 0];
        float2 e1 = g_edges[e + 1];
        float2 e2 = g_edges[e + 2];
        float2 e3 = g_edges[e + 3];
        float4 v0 = hb[(size_t)__float_as_int(e0.x) * 32 + lane];
        float4 v1 = hb[(size_t)__float_as_int(e1.x) * 32 + lane];
        float4 v2 = hb[(size_t)__float_as_int(e2.x) * 32 + lane];
        float4 v3 = hb[(size_t)__float_as_int(e3.x) * 32 + lane];
        acc.x += v0.x * e0.y; acc.y += v0.y * e0.y; acc.z += v0.z * e0.y; acc.w += v0.w * e0.y;
        acc.x += v1.x * e1.y; acc.y += v1.y * e1.y; acc.z += v1.z * e1.y; acc.w += v1.w * e1.y;
        acc.x += v2.x * e2.y; acc.y += v2.y * e2.y; acc.z += v2.z * e2.y; acc.w += v2.w * e2.y;
        acc.x += v3.x * e3.y; acc.y += v3.y * e3.y; acc.z += v3.z * e3.y; acc.w += v3.w * e3.y;
    }
    for (; e < end; e++) {
        float2 ed = g_edges[e];
        float4 v = hb[(size_t)__float_as_int(ed.x) * 32 + lane];
        acc.x += v.x * ed.y; acc.y += v.y * ed.y; acc.z += v.z * ed.y; acc.w += v.w * ed.y;
    }

    ((float4*)out)[(size_t)node * 32 + lane] = acc;
}

// ---------------- launch ----------------

extern "C" void kernel_launch(void* const* d_in, const int* in_sizes, int n_in,
                              void* d_out, int out_size) {
    const float* x    = (const float*)d_in[0];
    const int*   ei   = (const int*)  d_in[1];
    const float* W1   = (const float*)d_in[2];
    const float* b1   = (const float*)d_in[3];
    const float* W2   = (const float*)d_in[4];
    const float* b2   = (const float*)d_in[5];
    const float* Wout = (const float*)d_in[6];
    const float* bout = (const float*)d_in[7];

    const int n = in_sizes[0] / D;
    const int E = in_sizes[1] / 2;
    const int* src = ei;
    const int* dst = ei + E;

    float *h1, *agg1, *h2, *agg2;
    cudaGetSymbolAddress((void**)&h1,   g_h1);
    cudaGetSymbolAddress((void**)&agg1, g_agg1);
    cudaGetSymbolAddress((void**)&h2,   g_h2);
    cudaGetSymbolAddress((void**)&agg2, g_agg2);

    // CSR build: degrees -> dinv -> rowptr -> scatter (weights precomputed)
    zero_kernel<<<(n + 255) / 256, 256>>>(n);
    count_deg_kernel<<<(E + 255) / 256, 256>>>(dst, E);
    dinv_kernel<<<(n + 255) / 256, 256>>>(n);
    scan_kernel<<<1, 1024>>>(n);
    scatter_kernel<<<(E + 255) / 256, 256>>>(src, dst, E);

    const int gemm_blocks = (n + 63) / 64;
    const int agg_blocks  = (n + 7) / 8;     // 8 warps (nodes) per 256-thread block

    // layer 1
    gemm_kernel<128, 4, 0, false><<<gemm_blocks, 256>>>(x, W1, nullptr, nullptr, h1, n);
    agg_kernel<<<agg_blocks, 256>>>(h1, agg1, n);

    // layer 2 (relu(agg1 + b1) fused into GEMM input)
    gemm_kernel<128, 4, 1, false><<<gemm_blocks, 256>>>(agg1, W2, b1, nullptr, h2, n);
    agg_kernel<<<agg_blocks, 256>>>(h2, agg2, n);

    // output layer: (agg2 + b2) @ Wout + bout
    gemm_kernel<40, 5, 2, true><<<gemm_blocks, 256>>>(agg2, Wout, b2, bout,
                                                      (float*)d_out, n);
}

// round 5
// speedup vs baseline: 3.0917x; 1.2921x over previous
#include <cuda_runtime.h>
#include <cuda_bf16.h>

#define N_MAX 100000
#define E_MAX 1700000
#define D 128

// Scratch (device globals: no allocation allowed in kernel_launch)
__device__ float  g_h1[(size_t)N_MAX * D];
__device__ float  g_agg1[(size_t)N_MAX * D];
__device__ float  g_h2[(size_t)N_MAX * D];
__device__ float  g_agg2[(size_t)N_MAX * D];
__device__ float  g_dinv[N_MAX];
__device__ int    g_deg[N_MAX];
__device__ int    g_fill[N_MAX];
__device__ int    g_rowptr[N_MAX];
__device__ int    g_ecnt;
__device__ float2 g_edges[E_MAX];   // .x = src (bits), .y = weight

// ---------------- helpers ----------------

__device__ __forceinline__ unsigned smem_u32(const void* p) {
    return (unsigned)__cvta_generic_to_shared(p);
}
__device__ __forceinline__ void cp_async16(unsigned dst, const void* src, int szbytes) {
    asm volatile("cp.async.cg.shared.global [%0], [%1], 16, %2;\n"
                 :: "r"(dst), "l"(src), "r"(szbytes));
}
__device__ __forceinline__ void cp_commit() {
    asm volatile("cp.async.commit_group;\n" ::);
}
__device__ __forceinline__ void cp_wait0() {
    asm volatile("cp.async.wait_group 0;\n" ::);
}

// ---------------- degree / norm / row offsets ----------------

__global__ void zero_kernel(int n) {
    int i = blockIdx.x * blockDim.x + threadIdx.x;
    if (i < n) { g_deg[i] = 0; g_fill[i] = 0; }
    if (i == 0) g_ecnt = 0;
}

__global__ void count_deg_kernel(const int* __restrict__ dst, int E) {
    int e = blockIdx.x * blockDim.x + threadIdx.x;
    if (e < E) atomicAdd(&g_deg[dst[e]], 1);
}

// dinv + CSR row offsets via atomic bump (order of segments is irrelevant)
__global__ void dinv_rowstart_kernel(int n) {
    int i = blockIdx.x * blockDim.x + threadIdx.x;
    if (i < n) {
        int d = g_deg[i];
        g_dinv[i]   = rsqrtf((float)d + 1.0f);   // +1 self loop
        g_rowptr[i] = atomicAdd(&g_ecnt, d);
    }
}

// ---------------- scatter edges into CSR order with precomputed weight ------

__global__ void scatter_kernel(const int* __restrict__ src,
                               const int* __restrict__ dst, int E) {
    int e = blockIdx.x * blockDim.x + threadIdx.x;
    if (e >= E) return;
    int s = src[e];
    int d = dst[e];
    int pos = g_rowptr[d] + atomicAdd(&g_fill[d], 1);
    g_edges[pos] = make_float2(__int_as_float(s), g_dinv[s] * g_dinv[d]);
}

// ---------------- GEMM (NCOL=128): out = in @ W, cp.async double-buffered ----

__global__ __launch_bounds__(256, 3)
void gemm128_kernel(const float* __restrict__ in, const float* __restrict__ W,
                    float* __restrict__ out, int n) {
    __shared__ float ws[2][32 * 128];   // 2 x 16KB
    __shared__ float xs[2][64 * 32];    // 2 x  8KB   (total 48KB)
    const int tid  = threadIdx.x;
    const int tcol = tid & 31;          // 32 col groups x 4 cols
    const int trow = tid >> 5;          // 8 row groups x 8 rows
    const int row0 = blockIdx.x * 64;

    float acc[8][4];
#pragma unroll
    for (int i = 0; i < 8; i++)
#pragma unroll
        for (int j = 0; j < 4; j++) acc[i][j] = 0.0f;

    auto issue_tile = [&](int t) {
        const int k0  = t * 32;
        const int buf = t & 1;
        unsigned wdst = smem_u32(&ws[buf][0]);
        const char* wsrc = (const char*)(W + (size_t)k0 * 128);
#pragma unroll
        for (int j = 0; j < 4; j++) {
            int u = tid + j * 256;                 // float4 index in 32x128 tile
            cp_async16(wdst + u * 16, wsrc + (size_t)u * 16, 16);
        }
        unsigned xdst = smem_u32(&xs[buf][0]);
#pragma unroll
        for (int j = 0; j < 2; j++) {
            int u = tid + j * 256;                 // float4 index in 64x32 tile
            int e = u * 4;
            int r = e >> 5, kk = e & 31;
            int row = row0 + r;
            int ok = (row < n);
            const char* xsrc = (const char*)(in + (size_t)(ok ? row : 0) * 128 + k0 + kk);
            cp_async16(xdst + u * 16, xsrc, ok ? 16 : 0);   // size 0 -> zero-fill
        }
        cp_commit();
    };

    issue_tile(0);
    cp_wait0();
    __syncthreads();

    for (int t = 0; t < 4; t++) {
        if (t < 3) issue_tile(t + 1);
        const float* wsb = ws[t & 1];
        const float* xsb = xs[t & 1];
#pragma unroll
        for (int kk = 0; kk < 32; kk++) {
            float4 wv = *(const float4*)(wsb + kk * 128 + tcol * 4);
            float xv[8];
#pragma unroll
            for (int i = 0; i < 8; i++) xv[i] = xsb[(trow * 8 + i) * 32 + kk];
#pragma unroll
            for (int i = 0; i < 8; i++) {
                acc[i][0] += xv[i] * wv.x;
                acc[i][1] += xv[i] * wv.y;
                acc[i][2] += xv[i] * wv.z;
                acc[i][3] += xv[i] * wv.w;
            }
        }
        cp_wait0();
        __syncthreads();
    }

#pragma unroll
    for (int i = 0; i < 8; i++) {
        int row = row0 + trow * 8 + i;
        if (row < n)
            *(float4*)(out + (size_t)row * 128 + tcol * 4) =
                make_float4(acc[i][0], acc[i][1], acc[i][2], acc[i][3]);
    }
}

// ---------------- GEMM (small NCOL): out[n, NCOL] = in @ W (+ bout) ---------

template<int NCOL, int TN, bool OUTBIAS>
__global__ void gemm_kernel(const float* __restrict__ in,
                            const float* __restrict__ W,
                            const float* __restrict__ bout,
                            float* __restrict__ out, int n) {
    constexpr int KT    = 32;
    constexpr int BROWS = 64;
    constexpr int CG    = NCOL / TN;
    constexpr int RG    = 256 / CG;
    constexpr int TM    = BROWS / RG;

    __shared__ float ws[KT][NCOL];
    __shared__ float xs[BROWS][KT];

    const int tid  = threadIdx.x;
    const int tcol = tid % CG;
    const int trow = tid / CG;
    const int row0 = blockIdx.x * BROWS;

    float acc[TM][TN];
#pragma unroll
    for (int i = 0; i < TM; i++)
#pragma unroll
        for (int j = 0; j < TN; j++) acc[i][j] = 0.0f;

    for (int k0 = 0; k0 < 128; k0 += KT) {
        for (int i = tid; i < KT * NCOL; i += 256) {
            int kk = i / NCOL, c = i % NCOL;
            ws[kk][c] = W[(size_t)(k0 + kk) * NCOL + c];
        }
        for (int i = tid; i < BROWS * KT; i += 256) {
            int r = i / KT, kk = i % KT;
            int row = row0 + r;
            xs[r][kk] = (row < n) ? in[(size_t)row * 128 + k0 + kk] : 0.0f;
        }
        __syncthreads();

#pragma unroll
        for (int kk = 0; kk < KT; kk++) {
            float wv[TN], xv[TM];
#pragma unroll
            for (int j = 0; j < TN; j++) wv[j] = ws[kk][tcol * TN + j];
#pragma unroll
            for (int i = 0; i < TM; i++) xv[i] = xs[trow * TM + i][kk];
#pragma unroll
            for (int i = 0; i < TM; i++)
#pragma unroll
                for (int j = 0; j < TN; j++) acc[i][j] += xv[i] * wv[j];
        }
        __syncthreads();
    }

#pragma unroll
    for (int i = 0; i < TM; i++) {
        int row = row0 + trow * TM + i;
        if (row < n) {
#pragma unroll
            for (int j = 0; j < TN; j++) {
                float v = acc[i][j];
                if (OUTBIAS) v += bout[tcol * TN + j];
                out[(size_t)row * NCOL + tcol * TN + j] = v;
            }
        }
    }
}

// ---------------- aggregation: one warp per node, no float atomics ----------
// out[node] = EPI( h[node]*dinv^2 + sum_e h[src_e]*w_e )
// EPI: 0 = none, 1 = relu(v + bin), 2 = v + bin

template<int EPI>
__global__ void agg_kernel(const float* __restrict__ h,
                           const float* __restrict__ bin,
                           float* __restrict__ out, int n) {
    int warp = (blockIdx.x * blockDim.x + threadIdx.x) >> 5;
    if (warp >= n) return;
    const int node = warp;
    const int lane = threadIdx.x & 31;

    const float4* hb = (const float4*)h;
    float di = g_dinv[node];
    float w0 = di * di;
    float4 acc = hb[(size_t)node * 32 + lane];
    acc.x *= w0; acc.y *= w0; acc.z *= w0; acc.w *= w0;

    int e   = g_rowptr[node];
    int end = e + g_deg[node];

    for (; e + 4 <= end; e += 4) {
        float2 e0 = g_edges[e + 0];
        float2 e1 = g_edges[e + 1];
        float2 e2 = g_edges[e + 2];
        float2 e3 = g_edges[e + 3];
        float4 v0 = hb[(size_t)__float_as_int(e0.x) * 32 + lane];
        float4 v1 = hb[(size_t)__float_as_int(e1.x) * 32 + lane];
        float4 v2 = hb[(size_t)__float_as_int(e2.x) * 32 + lane];
        float4 v3 = hb[(size_t)__float_as_int(e3.x) * 32 + lane];
        acc.x += v0.x * e0.y; acc.y += v0.y * e0.y; acc.z += v0.z * e0.y; acc.w += v0.w * e0.y;
        acc.x += v1.x * e1.y; acc.y += v1.y * e1.y; acc.z += v1.z * e1.y; acc.w += v1.w * e1.y;
        acc.x += v2.x * e2.y; acc.y += v2.y * e2.y; acc.z += v2.z * e2.y; acc.w += v2.w * e2.y;
        acc.x += v3.x * e3.y; acc.y += v3.y * e3.y; acc.z += v3.z * e3.y; acc.w += v3.w * e3.y;
    }
    for (; e < end; e++) {
        float2 ed = g_edges[e];
        float4 v = hb[(size_t)__float_as_int(ed.x) * 32 + lane];
        acc.x += v.x * ed.y; acc.y += v.y * ed.y; acc.z += v.z * ed.y; acc.w += v.w * ed.y;
    }

    if (EPI != 0) {
        float4 bb = ((const float4*)bin)[lane];
        acc.x += bb.x; acc.y += bb.y; acc.z += bb.z; acc.w += bb.w;
        if (EPI == 1) {
            acc.x = fmaxf(acc.x, 0.0f); acc.y = fmaxf(acc.y, 0.0f);
            acc.z = fmaxf(acc.z, 0.0f); acc.w = fmaxf(acc.w, 0.0f);
        }
    }

    ((float4*)out)[(size_t)node * 32 + lane] = acc;
}

// ---------------- launch ----------------

extern "C" void kernel_launch(void* const* d_in, const int* in_sizes, int n_in,
                              void* d_out, int out_size) {
    const float* x    = (const float*)d_in[0];
    const int*   ei   = (const int*)  d_in[1];
    const float* W1   = (const float*)d_in[2];
    const float* b1   = (const float*)d_in[3];
    const float* W2   = (const float*)d_in[4];
    const float* b2   = (const float*)d_in[5];
    const float* Wout = (const float*)d_in[6];
    const float* bout = (const float*)d_in[7];

    const int n = in_sizes[0] / D;
    const int E = in_sizes[1] / 2;
    const int* src = ei;
    const int* dst = ei + E;

    float *h1, *agg1, *h2, *agg2;
    cudaGetSymbolAddress((void**)&h1,   g_h1);
    cudaGetSymbolAddress((void**)&agg1, g_agg1);
    cudaGetSymbolAddress((void**)&h2,   g_h2);
    cudaGetSymbolAddress((void**)&agg2, g_agg2);

    // CSR build: degrees -> dinv + row offsets (atomic bump) -> scatter
    zero_kernel<<<(n + 255) / 256, 256>>>(n);
    count_deg_kernel<<<(E + 255) / 256, 256>>>(dst, E);
    dinv_rowstart_kernel<<<(n + 255) / 256, 256>>>(n);
    scatter_kernel<<<(E + 255) / 256, 256>>>(src, dst, E);

    const int gemm_blocks = (n + 63) / 64;
    const int agg_blocks  = (n + 7) / 8;     // 8 warps (nodes) per 256-thread block

    // layer 1:  h1 = x @ W1 ; agg1 = relu(A h1 + b1)
    gemm128_kernel<<<gemm_blocks, 256>>>(x, W1, h1, n);
    agg_kernel<1><<<agg_blocks, 256>>>(h1, b1, agg1, n);

    // layer 2:  h2 = agg1 @ W2 ; agg2 = A h2 + b2
    gemm128_kernel<<<gemm_blocks, 256>>>(agg1, W2, h2, n);
    agg_kernel<2><<<agg_blocks, 256>>>(h2, b2, agg2, n);

    // output:  out = agg2 @ Wout + bout
    gemm_kernel<40, 5, true><<<gemm_blocks, 256>>>(agg2, Wout, bout, (float*)d_out, n);
}

// round 7
// speedup vs baseline: 3.6971x; 1.1958x over previous
#include <cuda_runtime.h>
#include <cuda_bf16.h>

#define N_MAX 100000
#define E_MAX 1700000
#define D 128

// Scratch (device globals: no allocation allowed in kernel_launch)
__device__ float  g_h1[(size_t)N_MAX * D];    // hw1 = (x@W1)*dinv[row]
__device__ float  g_agg1[(size_t)N_MAX * D];
__device__ float  g_h2[(size_t)N_MAX * D];    // hw2 = (agg1@W2)*dinv[row]
__device__ float  g_agg2[(size_t)N_MAX * D];
__device__ float  g_dinv[N_MAX];
__device__ int    g_deg[N_MAX];
__device__ int    g_fill[N_MAX];
__device__ int    g_rowptr[N_MAX];
__device__ int    g_ecnt;
__device__ int    g_esrc[E_MAX];              // CSR: src only (weights are algebraic now)

// ---------------- helpers ----------------

__device__ __forceinline__ unsigned smem_u32(const void* p) {
    return (unsigned)__cvta_generic_to_shared(p);
}
__device__ __forceinline__ void cp_async16(unsigned dst, const void* src, int szbytes) {
    asm volatile("cp.async.cg.shared.global [%0], [%1], 16, %2;\n"
                 :: "r"(dst), "l"(src), "r"(szbytes));
}
__device__ __forceinline__ void cp_commit() {
    asm volatile("cp.async.commit_group;\n" ::);
}
__device__ __forceinline__ void cp_wait0() {
    asm volatile("cp.async.wait_group 0;\n" ::);
}
__device__ __forceinline__ unsigned f2tf32(float f) {
    unsigned r; asm("cvt.rna.tf32.f32 %0, %1;" : "=r"(r) : "f"(f)); return r;
}
__device__ __forceinline__ void mma_tf32(float& c0, float& c1, float& c2, float& c3,
                                         unsigned a0, unsigned a1, unsigned a2, unsigned a3,
                                         unsigned b0, unsigned b1) {
    asm volatile("mma.sync.aligned.m16n8k8.row.col.f32.tf32.tf32.f32 "
                 "{%0,%1,%2,%3}, {%4,%5,%6,%7}, {%8,%9}, {%0,%1,%2,%3};\n"
                 : "+f"(c0), "+f"(c1), "+f"(c2), "+f"(c3)
                 : "r"(a0), "r"(a1), "r"(a2), "r"(a3), "r"(b0), "r"(b1));
}

// ---------------- CSR build ----------------

__global__ void zero_kernel(int n) {
    int i = blockIdx.x * blockDim.x + threadIdx.x;
    if (i < n) { g_deg[i] = 0; g_fill[i] = 0; }
    if (i == 0) g_ecnt = 0;
}

__global__ void count_deg_kernel(const int* __restrict__ dst, int E) {
    int e = blockIdx.x * blockDim.x + threadIdx.x;
    if (e < E) atomicAdd(&g_deg[dst[e]], 1);
}

// dinv + CSR row offsets; block-aggregated bump (1 global atomic per 256 nodes)
__global__ void dinv_rowstart_kernel(int n) {
    __shared__ int wtot[8];
    __shared__ int base_sh;
    const int tid  = threadIdx.x;
    const int lane = tid & 31;
    const int wid  = tid >> 5;
    int i = blockIdx.x * 256 + tid;
    int d = (i < n) ? g_deg[i] : 0;

    int incl = d;
#pragma unroll
    for (int off = 1; off < 32; off <<= 1) {
        int t = __shfl_up_sync(0xFFFFFFFFu, incl, off);
        if (lane >= off) incl += t;
    }
    if (lane == 31) wtot[wid] = incl;
    __syncthreads();
    if (tid == 0) {
        int s = 0;
#pragma unroll
        for (int j = 0; j < 8; j++) { int t = wtot[j]; wtot[j] = s; s += t; }
        base_sh = atomicAdd(&g_ecnt, s);
    }
    __syncthreads();
    if (i < n) {
        g_dinv[i]   = rsqrtf((float)d + 1.0f);   // +1 self loop
        g_rowptr[i] = base_sh + wtot[wid] + (incl - d);
    }
}

__global__ void scatter_kernel(const int* __restrict__ src,
                               const int* __restrict__ dst, int E) {
    int e = blockIdx.x * blockDim.x + threadIdx.x;
    if (e >= E) return;
    int s = src[e];
    int d = dst[e];
    int pos = g_rowptr[d] + atomicAdd(&g_fill[d], 1);
    g_esrc[pos] = s;
}

// ---------------- GEMM 128x128 (3xTF32 tensor cores) -----------------------
// out[row,:] = (in[row,:] @ W) * (SCALE ? dinv[row] : 1)

constexpr int WPAD = 136;   // 32x128 W tile, padded row stride (words)
constexpr int XPAD = 36;    // 64x32  X tile, padded row stride (words)

template<bool SCALE>
__global__ __launch_bounds__(256, 3)
void gemm128_kernel(const float* __restrict__ in, const float* __restrict__ W,
                    float* __restrict__ out, int n) {
    __shared__ float ws[2][32 * WPAD];
    __shared__ float xs[2][64 * XPAD];

    const int tid    = threadIdx.x;
    const int lane   = tid & 31;
    const int warp   = tid >> 5;
    const int warp_m = warp & 3;          // 4 warps over 64 rows (16 each)
    const int warp_n = warp >> 2;         // 2 warps over 128 cols (64 each)
    const int g      = lane >> 2;         // groupID 0..7
    const int tig    = lane & 3;          // thread-in-group 0..3
    const int row0   = blockIdx.x * 64;
    const int rbase  = warp_m * 16;
    const int nbase  = warp_n * 64;

    float acc[8][4];
#pragma unroll
    for (int i = 0; i < 8; i++)
#pragma unroll
        for (int j = 0; j < 4; j++) acc[i][j] = 0.0f;

    auto issue_tile = [&](int t) {
        const int k0  = t * 32;
        const int buf = t & 1;
        unsigned wdst = smem_u32(&ws[buf][0]);
        const char* wsrc = (const char*)(W + (size_t)k0 * 128);
#pragma unroll
        for (int j = 0; j < 4; j++) {
            int u = tid + j * 256;               // float4 index into 32x32(f4) tile
            int r = u >> 5, c4 = u & 31;
            cp_async16(wdst + (r * WPAD + c4 * 4) * 4,
                       wsrc + (size_t)(r * 128 + c4 * 4) * 4, 16);
        }
        unsigned xdst = smem_u32(&xs[buf][0]);
#pragma unroll
        for (int j = 0; j < 2; j++) {
            int u = tid + j * 256;               // float4 index into 64x8(f4) tile
            int r = u >> 3, c4 = u & 7;
            int row = row0 + r;
            int ok = (row < n);
            const char* xsrc = (const char*)(in + (size_t)(ok ? row : 0) * 128 + k0 + c4 * 4);
            cp_async16(xdst + (r * XPAD + c4 * 4) * 4, xsrc, ok ? 16 : 0);
        }
        cp_commit();
    };

    issue_tile(0);
    cp_wait0();
    __syncthreads();

    for (int t = 0; t < 4; t++) {
        if (t < 3) issue_tile(t + 1);
        const float* wsb = ws[t & 1];
        const float* xsb = xs[t & 1];
#pragma unroll
        for (int ks = 0; ks < 4; ks++) {
            const int kk0 = ks * 8;
            // A fragment (16x8), split hi/lo
            float a0f = xsb[(rbase + g)     * XPAD + kk0 + tig];
            float a1f = xsb[(rbase + g + 8) * XPAD + kk0 + tig];
            float a2f = xsb[(rbase + g)     * XPAD + kk0 + tig + 4];
            float a3f = xsb[(rbase + g + 8) * XPAD + kk0 + tig + 4];
            unsigned ah0 = f2tf32(a0f), ah1 = f2tf32(a1f),
                     ah2 = f2tf32(a2f), ah3 = f2tf32(a3f);
            unsigned al0 = __float_as_uint(a0f - __uint_as_float(ah0));
            unsigned al1 = __float_as_uint(a1f - __uint_as_float(ah1));
            unsigned al2 = __float_as_uint(a2f - __uint_as_float(ah2));
            unsigned al3 = __float_as_uint(a3f - __uint_as_float(ah3));
#pragma unroll
            for (int nt = 0; nt < 8; nt++) {
                const int n0 = nbase + nt * 8;
                float b0f = wsb[(kk0 + tig)     * WPAD + n0 + g];
                float b1f = wsb[(kk0 + tig + 4) * WPAD + n0 + g];
                unsigned bh0 = f2tf32(b0f), bh1 = f2tf32(b1f);
                unsigned bl0 = __float_as_uint(b0f - __uint_as_float(bh0));
                unsigned bl1 = __float_as_uint(b1f - __uint_as_float(bh1));
                mma_tf32(acc[nt][0], acc[nt][1], acc[nt][2], acc[nt][3],
                         ah0, ah1, ah2, ah3, bh0, bh1);
                mma_tf32(acc[nt][0], acc[nt][1], acc[nt][2], acc[nt][3],
                         al0, al1, al2, al3, bh0, bh1);
                mma_tf32(acc[nt][0], acc[nt][1], acc[nt][2], acc[nt][3],
                         ah0, ah1, ah2, ah3, bl0, bl1);
            }
        }
        cp_wait0();
        __syncthreads();
    }

    const int rowA = row0 + rbase + g;
    const int rowB = rowA + 8;
    float dvA = 1.0f, dvB = 1.0f;
    if (SCALE) {
        if (rowA < n) dvA = g_dinv[rowA];
        if (rowB < n) dvB = g_dinv[rowB];
    }
#pragma unroll
    for (int nt = 0; nt < 8; nt++) {
        const int cn = nbase + nt * 8 + tig * 2;
        if (rowA < n)
            *(float2*)(out + (size_t)rowA * 128 + cn) =
                make_float2(acc[nt][0] * dvA, acc[nt][1] * dvA);
        if (rowB < n)
            *(float2*)(out + (size_t)rowB * 128 + cn) =
                make_float2(acc[nt][2] * dvB, acc[nt][3] * dvB);
    }
}

// ---------------- GEMM (NCOL=40): out = in @ W + bout ----------------------

template<int NCOL, int TN, bool OUTBIAS>
__global__ void gemm_kernel(const float* __restrict__ in,
                            const float* __restrict__ W,
                            const float* __restrict__ bout,
                            float* __restrict__ out, int n) {
    constexpr int KT    = 32;
    constexpr int BROWS = 64;
    constexpr int CG    = NCOL / TN;
    constexpr int RG    = 256 / CG;
    constexpr int TM    = BROWS / RG;

    __shared__ float ws[KT][NCOL];
    __shared__ float xs[BROWS][KT];

    const int tid  = threadIdx.x;
    const int tcol = tid % CG;
    const int trow = tid / CG;
    const int row0 = blockIdx.x * BROWS;

    float acc[TM][TN];
#pragma unroll
    for (int i = 0; i < TM; i++)
#pragma unroll
        for (int j = 0; j < TN; j++) acc[i][j] = 0.0f;

    for (int k0 = 0; k0 < 128; k0 += KT) {
        for (int i = tid; i < KT * NCOL; i += 256) {
            int kk = i / NCOL, c = i % NCOL;
            ws[kk][c] = W[(size_t)(k0 + kk) * NCOL + c];
        }
        for (int i = tid; i < BROWS * KT; i += 256) {
            int r = i / KT, kk = i % KT;
            int row = row0 + r;
            xs[r][kk] = (row < n) ? in[(size_t)row * 128 + k0 + kk] : 0.0f;
        }
        __syncthreads();

#pragma unroll
        for (int kk = 0; kk < KT; kk++) {
            float wv[TN], xv[TM];
#pragma unroll
            for (int j = 0; j < TN; j++) wv[j] = ws[kk][tcol * TN + j];
#pragma unroll
            for (int i = 0; i < TM; i++) xv[i] = xs[trow * TM + i][kk];
#pragma unroll
            for (int i = 0; i < TM; i++)
#pragma unroll
                for (int j = 0; j < TN; j++) acc[i][j] += xv[i] * wv[j];
        }
        __syncthreads();
    }

#pragma unroll
    for (int i = 0; i < TM; i++) {
        int row = row0 + trow * TM + i;
        if (row < n) {
#pragma unroll
            for (int j = 0; j < TN; j++) {
                float v = acc[i][j];
                if (OUTBIAS) v += bout[tcol * TN + j];
                out[(size_t)row * NCOL + tcol * TN + j] = v;
            }
        }
    }
}

// ---------------- aggregation: one warp per node ----------------------------
// in:  hw = h * dinv[row]   (scaled in GEMM epilogue)
// out[node] = EPI( dinv[node] * (hw[node] + sum_e hw[src_e]) + bin )
// EPI: 1 = relu(v + bin), 2 = v + bin

template<int EPI>
__global__ void agg_kernel(const float* __restrict__ hw,
                           const float* __restrict__ bin,
                           float* __restrict__ out, int n) {
    int warp = (blockIdx.x * blockDim.x + threadIdx.x) >> 5;
    if (warp >= n) return;
    const int node = warp;
    const int lane = threadIdx.x & 31;

    const float4* hb = (const float4*)hw;
    float4 acc = hb[(size_t)node * 32 + lane];    // self (hw includes dinv[node])

    int e   = g_rowptr[node];
    int end = e + g_deg[node];

    for (; e + 4 <= end; e += 4) {
        int s0 = g_esrc[e + 0];
        int s1 = g_esrc[e + 1];
        int s2 = g_esrc[e + 2];
        int s3 = g_esrc[e + 3];
        float4 v0 = hb[(size_t)s0 * 32 + lane];
        float4 v1 = hb[(size_t)s1 * 32 + lane];
        float4 v2 = hb[(size_t)s2 * 32 + lane];
        float4 v3 = hb[(size_t)s3 * 32 + lane];
        acc.x += v0.x + v1.x + v2.x + v3.x;
        acc.y += v0.y + v1.y + v2.y + v3.y;
        acc.z += v0.z + v1.z + v2.z + v3.z;
        acc.w += v0.w + v1.w + v2.w + v3.w;
    }
    for (; e < end; e++) {
        float4 v = hb[(size_t)g_esrc[e] * 32 + lane];
        acc.x += v.x; acc.y += v.y; acc.z += v.z; acc.w += v.w;
    }

    float dv = g_dinv[node];
    float4 bb = ((const float4*)bin)[lane];
    acc.x = acc.x * dv + bb.x;
    acc.y = acc.y * dv + bb.y;
    acc.z = acc.z * dv + bb.z;
    acc.w = acc.w * dv + bb.w;
    if (EPI == 1) {
        acc.x = fmaxf(acc.x, 0.0f); acc.y = fmaxf(acc.y, 0.0f);
        acc.z = fmaxf(acc.z, 0.0f); acc.w = fmaxf(acc.w, 0.0f);
    }

    ((float4*)out)[(size_t)node * 32 + lane] = acc;
}

// ---------------- launch ----------------

extern "C" void kernel_launch(void* const* d_in, const int* in_sizes, int n_in,
                              void* d_out, int out_size) {
    const float* x    = (const float*)d_in[0];
    const int*   ei   = (const int*)  d_in[1];
    const float* W1   = (const float*)d_in[2];
    const float* b1   = (const float*)d_in[3];
    const float* W2   = (const float*)d_in[4];
    const float* b2   = (const float*)d_in[5];
    const float* Wout = (const float*)d_in[6];
    const float* bout = (const float*)d_in[7];

    const int n = in_sizes[0] / D;
    const int E = in_sizes[1] / 2;
    const int* src = ei;
    const int* dst = ei + E;

    float *h1, *agg1, *h2, *agg2;
    cudaGetSymbolAddress((void**)&h1,   g_h1);
    cudaGetSymbolAddress((void**)&agg1, g_agg1);
    cudaGetSymbolAddress((void**)&h2,   g_h2);
    cudaGetSymbolAddress((void**)&agg2, g_agg2);

    // CSR build: degrees -> dinv + row offsets -> scatter (src only)
    zero_kernel<<<(n + 255) / 256, 256>>>(n);
    count_deg_kernel<<<(E + 255) / 256, 256>>>(dst, E);
    dinv_rowstart_kernel<<<(n + 255) / 256, 256>>>(n);
    scatter_kernel<<<(E + 255) / 256, 256>>>(src, dst, E);

    const int gemm_blocks = (n + 63) / 64;
    const int agg_blocks  = (n + 7) / 8;

    // layer 1:  hw1 = (x @ W1) * dinv ; agg1 = relu(dinv*(S hw1) + b1)
    gemm128_kernel<true><<<gemm_blocks, 256>>>(x, W1, h1, n);
    agg_kernel<1><<<agg_blocks, 256>>>(h1, b1, agg1, n);

    // layer 2:  hw2 = (agg1 @ W2) * dinv ; agg2 = dinv*(S hw2) + b2
    gemm128_kernel<true><<<gemm_blocks, 256>>>(agg1, W2, h2, n);
    agg_kernel<2><<<agg_blocks, 256>>>(h2, b2, agg2, n);

    // output:  out = agg2 @ Wout + bout
    gemm_kernel<40, 5, true><<<gemm_blocks, 256>>>(agg2, Wout, bout, (float*)d_out, n);
}

// round 8
// speedup vs baseline: 3.8832x; 1.0503x over previous
#include <cuda_runtime.h>
#include <cuda_fp16.h>
#include <cuda_bf16.h>

#define N_MAX 100000
#define E_MAX 1700000
#define D 128

// Scratch (device globals: no allocation allowed in kernel_launch)
__device__ __half g_h1[(size_t)N_MAX * D];    // hw1 = (x@W1)*dinv[row]   (fp16)
__device__ float  g_agg1[(size_t)N_MAX * D];
__device__ __half g_h2[(size_t)N_MAX * D];    // hw2 = (agg1@W2)*dinv[row] (fp16)
__device__ float  g_agg2[(size_t)N_MAX * D];
__device__ float  g_dinv[N_MAX];
__device__ int    g_deg[N_MAX];
__device__ int    g_fill[N_MAX];
__device__ int    g_rowptr[N_MAX];
__device__ int    g_ecnt;
__device__ int    g_esrc[E_MAX];              // CSR: src only (weights are algebraic)

// ---------------- helpers ----------------

__device__ __forceinline__ unsigned smem_u32(const void* p) {
    return (unsigned)__cvta_generic_to_shared(p);
}
__device__ __forceinline__ void cp_async16(unsigned dst, const void* src, int szbytes) {
    asm volatile("cp.async.cg.shared.global [%0], [%1], 16, %2;\n"
                 :: "r"(dst), "l"(src), "r"(szbytes));
}
__device__ __forceinline__ void cp_commit() {
    asm volatile("cp.async.commit_group;\n" ::);
}
__device__ __forceinline__ void cp_wait0() {
    asm volatile("cp.async.wait_group 0;\n" ::);
}
__device__ __forceinline__ unsigned f2tf32(float f) {
    unsigned r; asm("cvt.rna.tf32.f32 %0, %1;" : "=r"(r) : "f"(f)); return r;
}
__device__ __forceinline__ void mma_tf32(float& c0, float& c1, float& c2, float& c3,
                                         unsigned a0, unsigned a1, unsigned a2, unsigned a3,
                                         unsigned b0, unsigned b1) {
    asm volatile("mma.sync.aligned.m16n8k8.row.col.f32.tf32.tf32.f32 "
                 "{%0,%1,%2,%3}, {%4,%5,%6,%7}, {%8,%9}, {%0,%1,%2,%3};\n"
                 : "+f"(c0), "+f"(c1), "+f"(c2), "+f"(c3)
                 : "r"(a0), "r"(a1), "r"(a2), "r"(a3), "r"(b0), "r"(b1));
}

// ---------------- CSR build ----------------

__global__ void zero_kernel(int n) {
    int i = blockIdx.x * blockDim.x + threadIdx.x;
    if (i < n) { g_deg[i] = 0; g_fill[i] = 0; }
    if (i == 0) g_ecnt = 0;
}

__global__ void count_deg_kernel(const int* __restrict__ dst, int E) {
    int e = blockIdx.x * blockDim.x + threadIdx.x;
    if (e < E) atomicAdd(&g_deg[dst[e]], 1);
}

// dinv + CSR row offsets; block-aggregated bump (1 global atomic per 256 nodes)
__global__ void dinv_rowstart_kernel(int n) {
    __shared__ int wtot[8];
    __shared__ int base_sh;
    const int tid  = threadIdx.x;
    const int lane = tid & 31;
    const int wid  = tid >> 5;
    int i = blockIdx.x * 256 + tid;
    int d = (i < n) ? g_deg[i] : 0;

    int incl = d;
#pragma unroll
    for (int off = 1; off < 32; off <<= 1) {
        int t = __shfl_up_sync(0xFFFFFFFFu, incl, off);
        if (lane >= off) incl += t;
    }
    if (lane == 31) wtot[wid] = incl;
    __syncthreads();
    if (tid == 0) {
        int s = 0;
#pragma unroll
        for (int j = 0; j < 8; j++) { int t = wtot[j]; wtot[j] = s; s += t; }
        base_sh = atomicAdd(&g_ecnt, s);
    }
    __syncthreads();
    if (i < n) {
        g_dinv[i]   = rsqrtf((float)d + 1.0f);   // +1 self loop
        g_rowptr[i] = base_sh + wtot[wid] + (incl - d);
    }
}

__global__ void scatter_kernel(const int* __restrict__ src,
                               const int* __restrict__ dst, int E) {
    int e = blockIdx.x * blockDim.x + threadIdx.x;
    if (e >= E) return;
    int s = src[e];
    int d = dst[e];
    int pos = g_rowptr[d] + atomicAdd(&g_fill[d], 1);
    g_esrc[pos] = s;
}

// ---------------- GEMM 128x128 (3xTF32 tensor cores), fp16 output ----------
// out_h[row,:] = half( (in[row,:] @ W) * dinv[row] )

constexpr int WPAD = 136;   // 32x128 W tile, padded row stride (words)
constexpr int XPAD = 36;    // 64x32  X tile, padded row stride (words)

__global__ __launch_bounds__(256, 3)
void gemm128_kernel(const float* __restrict__ in, const float* __restrict__ W,
                    __half* __restrict__ outh, int n) {
    __shared__ float ws[2][32 * WPAD];
    __shared__ float xs[2][64 * XPAD];

    const int tid    = threadIdx.x;
    const int lane   = tid & 31;
    const int warp   = tid >> 5;
    const int warp_m = warp & 3;          // 4 warps over 64 rows (16 each)
    const int warp_n = warp >> 2;         // 2 warps over 128 cols (64 each)
    const int g      = lane >> 2;         // groupID 0..7
    const int tig    = lane & 3;          // thread-in-group 0..3
    const int row0   = blockIdx.x * 64;
    const int rbase  = warp_m * 16;
    const int nbase  = warp_n * 64;

    float acc[8][4];
#pragma unroll
    for (int i = 0; i < 8; i++)
#pragma unroll
        for (int j = 0; j < 4; j++) acc[i][j] = 0.0f;

    auto issue_tile = [&](int t) {
        const int k0  = t * 32;
        const int buf = t & 1;
        unsigned wdst = smem_u32(&ws[buf][0]);
        const char* wsrc = (const char*)(W + (size_t)k0 * 128);
#pragma unroll
        for (int j = 0; j < 4; j++) {
            int u = tid + j * 256;               // float4 index into 32x32(f4) tile
            int r = u >> 5, c4 = u & 31;
            cp_async16(wdst + (r * WPAD + c4 * 4) * 4,
                       wsrc + (size_t)(r * 128 + c4 * 4) * 4, 16);
        }
        unsigned xdst = smem_u32(&xs[buf][0]);
#pragma unroll
        for (int j = 0; j < 2; j++) {
            int u = tid + j * 256;               // float4 index into 64x8(f4) tile
            int r = u >> 3, c4 = u & 7;
            int row = row0 + r;
            int ok = (row < n);
            const char* xsrc = (const char*)(in + (size_t)(ok ? row : 0) * 128 + k0 + c4 * 4);
            cp_async16(xdst + (r * XPAD + c4 * 4) * 4, xsrc, ok ? 16 : 0);
        }
        cp_commit();
    };

    issue_tile(0);
    cp_wait0();
    __syncthreads();

    for (int t = 0; t < 4; t++) {
        if (t < 3) issue_tile(t + 1);
        const float* wsb = ws[t & 1];
        const float* xsb = xs[t & 1];
#pragma unroll
        for (int ks = 0; ks < 4; ks++) {
            const int kk0 = ks * 8;
            // A fragment (16x8), split hi/lo
            float a0f = xsb[(rbase + g)     * XPAD + kk0 + tig];
            float a1f = xsb[(rbase + g + 8) * XPAD + kk0 + tig];
            float a2f = xsb[(rbase + g)     * XPAD + kk0 + tig + 4];
            float a3f = xsb[(rbase + g + 8) * XPAD + kk0 + tig + 4];
            unsigned ah0 = f2tf32(a0f), ah1 = f2tf32(a1f),
                     ah2 = f2tf32(a2f), ah3 = f2tf32(a3f);
            unsigned al0 = __float_as_uint(a0f - __uint_as_float(ah0));
            unsigned al1 = __float_as_uint(a1f - __uint_as_float(ah1));
            unsigned al2 = __float_as_uint(a2f - __uint_as_float(ah2));
            unsigned al3 = __float_as_uint(a3f - __uint_as_float(ah3));
#pragma unroll
            for (int nt = 0; nt < 8; nt++) {
                const int n0 = nbase + nt * 8;
                float b0f = wsb[(kk0 + tig)     * WPAD + n0 + g];
                float b1f = wsb[(kk0 + tig + 4) * WPAD + n0 + g];
                unsigned bh0 = f2tf32(b0f), bh1 = f2tf32(b1f);
                unsigned bl0 = __float_as_uint(b0f - __uint_as_float(bh0));
                unsigned bl1 = __float_as_uint(b1f - __uint_as_float(bh1));
                mma_tf32(acc[nt][0], acc[nt][1], acc[nt][2], acc[nt][3],
                         ah0, ah1, ah2, ah3, bh0, bh1);
                mma_tf32(acc[nt][0], acc[nt][1], acc[nt][2], acc[nt][3],
                         al0, al1, al2, al3, bh0, bh1);
                mma_tf32(acc[nt][0], acc[nt][1], acc[nt][2], acc[nt][3],
                         ah0, ah1, ah2, ah3, bl0, bl1);
            }
        }
        cp_wait0();
        __syncthreads();
    }

    const int rowA = row0 + rbase + g;
    const int rowB = rowA + 8;
    float dvA = (rowA < n) ? g_dinv[rowA] : 0.0f;
    float dvB = (rowB < n) ? g_dinv[rowB] : 0.0f;
#pragma unroll
    for (int nt = 0; nt < 8; nt++) {
        const int cn = nbase + nt * 8 + tig * 2;
        if (rowA < n)
            *(__half2*)(outh + (size_t)rowA * 128 + cn) =
                __floats2half2_rn(acc[nt][0] * dvA, acc[nt][1] * dvA);
        if (rowB < n)
            *(__half2*)(outh + (size_t)rowB * 128 + cn) =
                __floats2half2_rn(acc[nt][2] * dvB, acc[nt][3] * dvB);
    }
}

// ---------------- GEMM (NCOL=40): out = in @ W + bout ----------------------

template<int NCOL, int TN, bool OUTBIAS>
__global__ void gemm_kernel(const float* __restrict__ in,
                            const float* __restrict__ W,
                            const float* __restrict__ bout,
                            float* __restrict__ out, int n) {
    constexpr int KT    = 32;
    constexpr int BROWS = 64;
    constexpr int CG    = NCOL / TN;
    constexpr int RG    = 256 / CG;
    constexpr int TM    = BROWS / RG;

    __shared__ float ws[KT][NCOL];
    __shared__ float xs[BROWS][KT];

    const int tid  = threadIdx.x;
    const int tcol = tid % CG;
    const int trow = tid / CG;
    const int row0 = blockIdx.x * BROWS;

    float acc[TM][TN];
#pragma unroll
    for (int i = 0; i < TM; i++)
#pragma unroll
        for (int j = 0; j < TN; j++) acc[i][j] = 0.0f;

    for (int k0 = 0; k0 < 128; k0 += KT) {
        for (int i = tid; i < KT * NCOL; i += 256) {
            int kk = i / NCOL, c = i % NCOL;
            ws[kk][c] = W[(size_t)(k0 + kk) * NCOL + c];
        }
        for (int i = tid; i < BROWS * KT; i += 256) {
            int r = i / KT, kk = i % KT;
            int row = row0 + r;
            xs[r][kk] = (row < n) ? in[(size_t)row * 128 + k0 + kk] : 0.0f;
        }
        __syncthreads();

#pragma unroll
        for (int kk = 0; kk < KT; kk++) {
            float wv[TN], xv[TM];
#pragma unroll
            for (int j = 0; j < TN; j++) wv[j] = ws[kk][tcol * TN + j];
#pragma unroll
            for (int i = 0; i < TM; i++) xv[i] = xs[trow * TM + i][kk];
#pragma unroll
            for (int i = 0; i < TM; i++)
#pragma unroll
                for (int j = 0; j < TN; j++) acc[i][j] += xv[i] * wv[j];
        }
        __syncthreads();
    }

#pragma unroll
    for (int i = 0; i < TM; i++) {
        int row = row0 + trow * TM + i;
        if (row < n) {
#pragma unroll
            for (int j = 0; j < TN; j++) {
                float v = acc[i][j];
                if (OUTBIAS) v += bout[tcol * TN + j];
                out[(size_t)row * NCOL + tcol * TN + j] = v;
            }
        }
    }
}

// ---------------- aggregation: one warp per node, fp16 gather ---------------
// in:  hw (fp16) = h * dinv[row]
// out[node] = EPI( dinv[node] * (hw[node] + sum_e hw[src_e]) + bin )   (fp32)
// EPI: 1 = relu(v + bin), 2 = v + bin

__device__ __forceinline__ void acc_row(float4& acc, const uint2* hb,
                                        size_t node, int lane) {
    uint2 u = __ldg(&hb[node * 32 + lane]);
    float2 f0 = __half22float2(*reinterpret_cast<const __half2*>(&u.x));
    float2 f1 = __half22float2(*reinterpret_cast<const __half2*>(&u.y));
    acc.x += f0.x; acc.y += f0.y; acc.z += f1.x; acc.w += f1.y;
}

template<int EPI>
__global__ void agg_kernel(const __half* __restrict__ hw,
                           const float* __restrict__ bin,
                           float* __restrict__ out, int n) {
    int warp = (blockIdx.x * blockDim.x + threadIdx.x) >> 5;
    if (warp >= n) return;
    const int node = warp;
    const int lane = threadIdx.x & 31;

    const uint2* hb = (const uint2*)hw;   // 32 x 8B per 128-half row
    float4 acc = make_float4(0.f, 0.f, 0.f, 0.f);
    acc_row(acc, hb, (size_t)node, lane);          // self (hw includes dinv[node])

    int e   = g_rowptr[node];
    int end = e + g_deg[node];

    for (; e + 4 <= end; e += 4) {
        int s0 = g_esrc[e + 0];
        int s1 = g_esrc[e + 1];
        int s2 = g_esrc[e + 2];
        int s3 = g_esrc[e + 3];
        acc_row(acc, hb, (size_t)s0, lane);
        acc_row(acc, hb, (size_t)s1, lane);
        acc_row(acc, hb, (size_t)s2, lane);
        acc_row(acc, hb, (size_t)s3, lane);
    }
    for (; e < end; e++)
        acc_row(acc, hb, (size_t)g_esrc[e], lane);

    float dv = g_dinv[node];
    float4 bb = ((const float4*)bin)[lane];
    acc.x = acc.x * dv + bb.x;
    acc.y = acc.y * dv + bb.y;
    acc.z = acc.z * dv + bb.z;
    acc.w = acc.w * dv + bb.w;
    if (EPI == 1) {
        acc.x = fmaxf(acc.x, 0.0f); acc.y = fmaxf(acc.y, 0.0f);
        acc.z = fmaxf(acc.z, 0.0f); acc.w = fmaxf(acc.w, 0.0f);
    }

    ((float4*)out)[(size_t)node * 32 + lane] = acc;
}

// ---------------- launch ----------------

extern "C" void kernel_launch(void* const* d_in, const int* in_sizes, int n_in,
                              void* d_out, int out_size) {
    const float* x    = (const float*)d_in[0];
    const int*   ei   = (const int*)  d_in[1];
    const float* W1   = (const float*)d_in[2];
    const float* b1   = (const float*)d_in[3];
    const float* W2   = (const float*)d_in[4];
    const float* b2   = (const float*)d_in[5];
    const float* Wout = (const float*)d_in[6];
    const float* bout = (const float*)d_in[7];

    const int n = in_sizes[0] / D;
    const int E = in_sizes[1] / 2;
    const int* src = ei;
    const int* dst = ei + E;

    __half *h1, *h2;
    float *agg1, *agg2;
    cudaGetSymbolAddress((void**)&h1,   g_h1);
    cudaGetSymbolAddress((void**)&agg1, g_agg1);
    cudaGetSymbolAddress((void**)&h2,   g_h2);
    cudaGetSymbolAddress((void**)&agg2, g_agg2);

    // CSR build: degrees -> dinv + row offsets -> scatter (src only)
    zero_kernel<<<(n + 255) / 256, 256>>>(n);
    count_deg_kernel<<<(E + 255) / 256, 256>>>(dst, E);
    dinv_rowstart_kernel<<<(n + 255) / 256, 256>>>(n);
    scatter_kernel<<<(E + 255) / 256, 256>>>(src, dst, E);

    const int gemm_blocks = (n + 63) / 64;
    const int agg_blocks  = (n + 7) / 8;

    // layer 1:  hw1 = (x @ W1) * dinv ; agg1 = relu(dinv*(S hw1) + b1)
    gemm128_kernel<<<gemm_blocks, 256>>>(x, W1, h1, n);
    agg_kernel<1><<<agg_blocks, 256>>>(h1, b1, agg1, n);

    // layer 2:  hw2 = (agg1 @ W2) * dinv ; agg2 = dinv*(S hw2) + b2
    gemm128_kernel<<<gemm_blocks, 256>>>(agg1, W2, h2, n);
    agg_kernel<2><<<agg_blocks, 256>>>(h2, b2, agg2, n);

    // output:  out = agg2 @ Wout + bout
    gemm_kernel<40, 5, true><<<gemm_blocks, 256>>>(agg2, Wout, bout, (float*)d_out, n);
}

// round 10
// speedup vs baseline: 4.0977x; 1.0552x over previous
#include <cuda_runtime.h>
#include <cuda_fp16.h>
#include <cuda_bf16.h>
#include <cstdint>

#define N_MAX 100000
#define E_MAX 1700000
#define D 128

// Scratch (device globals: no allocation allowed in kernel_launch)
__device__ __half g_h1[(size_t)N_MAX * D];    // hw1 = (x@W1)*dinv[row]     (fp16)
__device__ __half g_agg1[(size_t)N_MAX * D];  // relu(dinv*S hw1 + b1)      (fp16)
__device__ __half g_h2[(size_t)N_MAX * D];    // hw2 = (agg1@W2)*dinv[row]  (fp16)
__device__ __half g_agg2[(size_t)N_MAX * D];  // dinv*S hw2 + b2            (fp16)
__device__ float  g_dinv[N_MAX];
__device__ int    g_deg[N_MAX];
__device__ int    g_fill[N_MAX];
__device__ int    g_rowptr[N_MAX];
__device__ int    g_ecnt;
__device__ int    g_esrc[E_MAX];              // CSR: src only (weights are algebraic)

// ---------------- helpers ----------------

__device__ __forceinline__ unsigned smem_u32(const void* p) {
    return (unsigned)__cvta_generic_to_shared(p);
}
__device__ __forceinline__ void cp_async16(unsigned dst, const void* src, int szbytes) {
    asm volatile("cp.async.cg.shared.global [%0], [%1], 16, %2;\n"
                 :: "r"(dst), "l"(src), "r"(szbytes));
}
__device__ __forceinline__ void cp_commit() {
    asm volatile("cp.async.commit_group;\n" ::);
}
__device__ __forceinline__ void cp_wait0() {
    asm volatile("cp.async.wait_group 0;\n" ::);
}
__device__ __forceinline__ unsigned f2tf32(float f) {
    unsigned r; asm("cvt.rna.tf32.f32 %0, %1;" : "=r"(r) : "f"(f)); return r;
}
__device__ __forceinline__ void mma_tf32(float& c0, float& c1, float& c2, float& c3,
                                         unsigned a0, unsigned a1, unsigned a2, unsigned a3,
                                         unsigned b0, unsigned b1) {
    asm volatile("mma.sync.aligned.m16n8k8.row.col.f32.tf32.tf32.f32 "
                 "{%0,%1,%2,%3}, {%4,%5,%6,%7}, {%8,%9}, {%0,%1,%2,%3};\n"
                 : "+f"(c0), "+f"(c1), "+f"(c2), "+f"(c3)
                 : "r"(a0), "r"(a1), "r"(a2), "r"(a3), "r"(b0), "r"(b1));
}

// ---------------- CSR build ----------------

__global__ void zero_kernel(int n) {
    int i = blockIdx.x * blockDim.x + threadIdx.x;
    if (i < n) { g_deg[i] = 0; g_fill[i] = 0; }
    if (i == 0) g_ecnt = 0;
}

// 4 edges per thread (int4 loads)
__global__ void count_deg_kernel4(const int* __restrict__ dst, int E) {
    int i = blockIdx.x * blockDim.x + threadIdx.x;
    int base = i * 4;
    if (base + 4 <= E) {
        int4 d4 = *(const int4*)(dst + base);
        atomicAdd(&g_deg[d4.x], 1);
        atomicAdd(&g_deg[d4.y], 1);
        atomicAdd(&g_deg[d4.z], 1);
        atomicAdd(&g_deg[d4.w], 1);
    } else {
        for (int e = base; e < E; e++) atomicAdd(&g_deg[dst[e]], 1);
    }
}
__global__ void count_deg_kernel1(const int* __restrict__ dst, int E) {
    int e = blockIdx.x * blockDim.x + threadIdx.x;
    if (e < E) atomicAdd(&g_deg[dst[e]], 1);
}

// dinv + CSR row offsets; block-aggregated bump (1 global atomic per 256 nodes)
__global__ void dinv_rowstart_kernel(int n) {
    __shared__ int wtot[8];
    __shared__ int base_sh;
    const int tid  = threadIdx.x;
    const int lane = tid & 31;
    const int wid  = tid >> 5;
    int i = blockIdx.x * 256 + tid;
    int d = (i < n) ? g_deg[i] : 0;

    int incl = d;
#pragma unroll
    for (int off = 1; off < 32; off <<= 1) {
        int t = __shfl_up_sync(0xFFFFFFFFu, incl, off);
        if (lane >= off) incl += t;
    }
    if (lane == 31) wtot[wid] = incl;
    __syncthreads();
    if (tid == 0) {
        int s = 0;
#pragma unroll
        for (int j = 0; j < 8; j++) { int t = wtot[j]; wtot[j] = s; s += t; }
        base_sh = atomicAdd(&g_ecnt, s);
    }
    __syncthreads();
    if (i < n) {
        g_dinv[i]   = rsqrtf((float)d + 1.0f);   // +1 self loop
        g_rowptr[i] = base_sh + wtot[wid] + (incl - d);
    }
}

__global__ void scatter_kernel4(const int* __restrict__ src,
                                const int* __restrict__ dst, int E) {
    int i = blockIdx.x * blockDim.x + threadIdx.x;
    int base = i * 4;
    if (base + 4 <= E) {
        int4 s4 = *(const int4*)(src + base);
        int4 d4 = *(const int4*)(dst + base);
        g_esrc[g_rowptr[d4.x] + atomicAdd(&g_fill[d4.x], 1)] = s4.x;
        g_esrc[g_rowptr[d4.y] + atomicAdd(&g_fill[d4.y], 1)] = s4.y;
        g_esrc[g_rowptr[d4.z] + atomicAdd(&g_fill[d4.z], 1)] = s4.z;
        g_esrc[g_rowptr[d4.w] + atomicAdd(&g_fill[d4.w], 1)] = s4.w;
    } else {
        for (int e = base; e < E; e++) {
            int s = src[e], d = dst[e];
            g_esrc[g_rowptr[d] + atomicAdd(&g_fill[d], 1)] = s;
        }
    }
}
__global__ void scatter_kernel1(const int* __restrict__ src,
                                const int* __restrict__ dst, int E) {
    int e = blockIdx.x * blockDim.x + threadIdx.x;
    if (e >= E) return;
    int s = src[e], d = dst[e];
    g_esrc[g_rowptr[d] + atomicAdd(&g_fill[d], 1)] = s;
}

// ---------------- GEMM 128x128 (TF32 tensor cores), fp16 output -------------
// out_h[row,:] = half( (in[row,:] @ W) * dinv[row] )
// FP32IN: fp32 input, 3-MMA split (AhBh + AlBh + AhBl)
// fp16 input: exact in tf32 -> 2-MMA split (AhBh + AhBl)

constexpr int WPAD  = 136;   // 32x128 W tile, padded row stride (floats)
constexpr int XPADF = 36;    // 64x32  X tile stride (floats)
constexpr int XPADH = 40;    // 64x32  X tile stride (halfs)

template<bool FP32IN>
__global__ __launch_bounds__(256, 3)
void gemm128_kernel(const void* __restrict__ in_, const float* __restrict__ W,
                    __half* __restrict__ outh, int n) {
    __shared__ float ws[2][32 * WPAD];
    __shared__ float xsf[FP32IN ? 2 * 64 * XPADF : 1];
    __shared__ __half xsh[FP32IN ? 1 : 2 * 64 * XPADH];

    const int tid    = threadIdx.x;
    const int lane   = tid & 31;
    const int warp   = tid >> 5;
    const int warp_m = warp & 3;          // 4 warps over 64 rows (16 each)
    const int warp_n = warp >> 2;         // 2 warps over 128 cols (64 each)
    const int g      = lane >> 2;         // groupID 0..7
    const int tig    = lane & 3;          // thread-in-group 0..3
    const int row0   = blockIdx.x * 64;
    const int rbase  = warp_m * 16;
    const int nbase  = warp_n * 64;

    float acc[8][4];
#pragma unroll
    for (int i = 0; i < 8; i++)
#pragma unroll
        for (int j = 0; j < 4; j++) acc[i][j] = 0.0f;

    auto issue_tile = [&](int t) {
        const int k0  = t * 32;
        const int buf = t & 1;
        unsigned wdst = smem_u32(&ws[buf][0]);
        const char* wsrc = (const char*)(W + (size_t)k0 * 128);
#pragma unroll
        for (int j = 0; j < 4; j++) {
            int u = tid + j * 256;               // float4 index into 32x32(f4) tile
            int r = u >> 5, c4 = u & 31;
            cp_async16(wdst + (r * WPAD + c4 * 4) * 4,
                       wsrc + (size_t)(r * 128 + c4 * 4) * 4, 16);
        }
        if (FP32IN) {
            const float* in = (const float*)in_;
            unsigned xdst = smem_u32(&xsf[buf * 64 * XPADF]);
#pragma unroll
            for (int j = 0; j < 2; j++) {
                int u = tid + j * 256;           // float4 index into 64x8(f4) tile
                int r = u >> 3, c4 = u & 7;
                int row = row0 + r;
                int ok = (row < n);
                const char* xsrc = (const char*)(in + (size_t)(ok ? row : 0) * 128 + k0 + c4 * 4);
                cp_async16(xdst + (r * XPADF + c4 * 4) * 4, xsrc, ok ? 16 : 0);
            }
        } else {
            const __half* in = (const __half*)in_;
            unsigned xdst = smem_u32(&xsh[buf * 64 * XPADH]);
            // 64 rows x 32 halfs; 16B = 8 halfs; 4 chunks/row; u in [0,256)
            int u = tid;
            int r = u >> 2, c8 = u & 3;
            int row = row0 + r;
            int ok = (row < n);
            const char* xsrc = (const char*)(in + (size_t)(ok ? row : 0) * 128 + k0 + c8 * 8);
            cp_async16(xdst + (r * XPADH + c8 * 8) * 2, xsrc, ok ? 16 : 0);
        }
        cp_commit();
    };

    issue_tile(0);
    cp_wait0();
    __syncthreads();

    for (int t = 0; t < 4; t++) {
        if (t < 3) issue_tile(t + 1);
        const float*  wsb  = ws[t & 1];
        const float*  xfb  = FP32IN ? &xsf[(t & 1) * 64 * XPADF] : nullptr;
        const __half* xhb  = FP32IN ? nullptr : &xsh[(t & 1) * 64 * XPADH];
#pragma unroll
        for (int ks = 0; ks < 4; ks++) {
            const int kk0 = ks * 8;
            float a0f, a1f, a2f, a3f;
            if (FP32IN) {
                a0f = xfb[(rbase + g)     * XPADF + kk0 + tig];
                a1f = xfb[(rbase + g + 8) * XPADF + kk0 + tig];
                a2f = xfb[(rbase + g)     * XPADF + kk0 + tig + 4];
                a3f = xfb[(rbase + g + 8) * XPADF + kk0 + tig + 4];
            } else {
                a0f = __half2float(xhb[(rbase + g)     * XPADH + kk0 + tig]);
                a1f = __half2float(xhb[(rbase + g + 8) * XPADH + kk0 + tig]);
                a2f = __half2float(xhb[(rbase + g)     * XPADH + kk0 + tig + 4]);
                a3f = __half2float(xhb[(rbase + g + 8) * XPADH + kk0 + tig + 4]);
            }
            unsigned ah0 = f2tf32(a0f), ah1 = f2tf32(a1f),
                     ah2 = f2tf32(a2f), ah3 = f2tf32(a3f);
            unsigned al0 = 0, al1 = 0, al2 = 0, al3 = 0;
            if (FP32IN) {
                al0 = __float_as_uint(a0f - __uint_as_float(ah0));
                al1 = __float_as_uint(a1f - __uint_as_float(ah1));
                al2 = __float_as_uint(a2f - __uint_as_float(ah2));
                al3 = __float_as_uint(a3f - __uint_as_float(ah3));
            }
#pragma unroll
            for (int nt = 0; nt < 8; nt++) {
                const int n0 = nbase + nt * 8;
                float b0f = wsb[(kk0 + tig)     * WPAD + n0 + g];
                float b1f = wsb[(kk0 + tig + 4) * WPAD + n0 + g];
                unsigned bh0 = f2tf32(b0f), bh1 = f2tf32(b1f);
                unsigned bl0 = __float_as_uint(b0f - __uint_as_float(bh0));
                unsigned bl1 = __float_as_uint(b1f - __uint_as_float(bh1));
                mma_tf32(acc[nt][0], acc[nt][1], acc[nt][2], acc[nt][3],
                         ah0, ah1, ah2, ah3, bh0, bh1);
                if (FP32IN)
                    mma_tf32(acc[nt][0], acc[nt][1], acc[nt][2], acc[nt][3],
                             al0, al1, al2, al3, bh0, bh1);
                mma_tf32(acc[nt][0], acc[nt][1], acc[nt][2], acc[nt][3],
                         ah0, ah1, ah2, ah3, bl0, bl1);
            }
        }
        cp_wait0();
        __syncthreads();
    }

    const int rowA = row0 + rbase + g;
    const int rowB = rowA + 8;
    float dvA = (rowA < n) ? g_dinv[rowA] : 0.0f;
    float dvB = (rowB < n) ? g_dinv[rowB] : 0.0f;
#pragma unroll
    for (int nt = 0; nt < 8; nt++) {
        const int cn = nbase + nt * 8 + tig * 2;
        if (rowA < n)
            *(__half2*)(outh + (size_t)rowA * 128 + cn) =
                __floats2half2_rn(acc[nt][0] * dvA, acc[nt][1] * dvA);
        if (rowB < n)
            *(__half2*)(outh + (size_t)rowB * 128 + cn) =
                __floats2half2_rn(acc[nt][2] * dvB, acc[nt][3] * dvB);
    }
}

// ---------------- GEMM (NCOL=40): out = in(fp16) @ W + bout ----------------

template<int NCOL, int TN, bool OUTBIAS>
__global__ void gemm_kernel(const __half* __restrict__ in,
                            const float* __restrict__ W,
                            const float* __restrict__ bout,
                            float* __restrict__ out, int n) {
    constexpr int KT    = 32;
    constexpr int BROWS = 64;
    constexpr int CG    = NCOL / TN;
    constexpr int RG    = 256 / CG;
    constexpr int TM    = BROWS / RG;

    __shared__ float ws[KT][NCOL];
    __shared__ float xs[BROWS][KT];

    const int tid  = threadIdx.x;
    const int tcol = tid % CG;
    const int trow = tid / CG;
    const int row0 = blockIdx.x * BROWS;

    float acc[TM][TN];
#pragma unroll
    for (int i = 0; i < TM; i++)
#pragma unroll
        for (int j = 0; j < TN; j++) acc[i][j] = 0.0f;

    for (int k0 = 0; k0 < 128; k0 += KT) {
        for (int i = tid; i < KT * NCOL; i += 256) {
            int kk = i / NCOL, c = i % NCOL;
            ws[kk][c] = W[(size_t)(k0 + kk) * NCOL + c];
        }
        // X tile: fp16 -> fp32, vectorized 8-half chunks
        for (int i = tid; i < BROWS * (KT / 8); i += 256) {
            int r = i / (KT / 8), c8 = i % (KT / 8);
            int row = row0 + r;
            float4 packed = (row < n)
                ? *(const float4*)(in + (size_t)row * 128 + k0 + c8 * 8)
                : make_float4(0.f, 0.f, 0.f, 0.f);
            const __half2* hp = (const __half2*)&packed;
#pragma unroll
            for (int j = 0; j < 4; j++) {
                float2 f = (row < n) ? __half22float2(hp[j]) : make_float2(0.f, 0.f);
                xs[r][c8 * 8 + j * 2]     = f.x;
                xs[r][c8 * 8 + j * 2 + 1] = f.y;
            }
        }
        __syncthreads();

#pragma unroll
        for (int kk = 0; kk < KT; kk++) {
            float wv[TN], xv[TM];
#pragma unroll
            for (int j = 0; j < TN; j++) wv[j] = ws[kk][tcol * TN + j];
#pragma unroll
            for (int i = 0; i < TM; i++) xv[i] = xs[trow * TM + i][kk];
#pragma unroll
            for (int i = 0; i < TM; i++)
#pragma unroll
                for (int j = 0; j < TN; j++) acc[i][j] += xv[i] * wv[j];
        }
        __syncthreads();
    }

#pragma unroll
    for (int i = 0; i < TM; i++) {
        int row = row0 + trow * TM + i;
        if (row < n) {
#pragma unroll
            for (int j = 0; j < TN; j++) {
                float v = acc[i][j];
                if (OUTBIAS) v += bout[tcol * TN + j];
                out[(size_t)row * NCOL + tcol * TN + j] = v;
            }
        }
    }
}

// ---------------- aggregation: one warp per node, fp16 gather/out -----------
// in:  hw (fp16) = h * dinv[row]
// out[node] (fp16) = EPI( dinv[node] * (hw[node] + sum_e hw[src_e]) + bin )
// EPI: 1 = relu(v + bin), 2 = v + bin

__device__ __forceinline__ void acc_row(float4& acc, const uint2* hb,
                                        size_t node, int lane) {
    uint2 u = __ldg(&hb[node * 32 + lane]);
    float2 f0 = __half22float2(*reinterpret_cast<const __half2*>(&u.x));
    float2 f1 = __half22float2(*reinterpret_cast<const __half2*>(&u.y));
    acc.x += f0.x; acc.y += f0.y; acc.z += f1.x; acc.w += f1.y;
}

template<int EPI>
__global__ void agg_kernel(const __half* __restrict__ hw,
                           const float* __restrict__ bin,
                           __half* __restrict__ out, int n) {
    int warp = (blockIdx.x * blockDim.x + threadIdx.x) >> 5;
    if (warp >= n) return;
    const int node = warp;
    const int lane = threadIdx.x & 31;

    const uint2* hb = (const uint2*)hw;   // 32 x 8B per 128-half row
    float4 acc = make_float4(0.f, 0.f, 0.f, 0.f);
    acc_row(acc, hb, (size_t)node, lane);          // self (hw includes dinv[node])

    int e   = g_rowptr[node];
    int end = e + g_deg[node];

    for (; e + 4 <= end; e += 4) {
        int s0 = g_esrc[e + 0];
        int s1 = g_esrc[e + 1];
        int s2 = g_esrc[e + 2];
        int s3 = g_esrc[e + 3];
        acc_row(acc, hb, (size_t)s0, lane);
        acc_row(acc, hb, (size_t)s1, lane);
        acc_row(acc, hb, (size_t)s2, lane);
        acc_row(acc, hb, (size_t)s3, lane);
    }
    for (; e < end; e++)
        acc_row(acc, hb, (size_t)g_esrc[e], lane);

    float dv = g_dinv[node];
    float4 bb = ((const float4*)bin)[lane];
    acc.x = acc.x * dv + bb.x;
    acc.y = acc.y * dv + bb.y;
    acc.z = acc.z * dv + bb.z;
    acc.w = acc.w * dv + bb.w;
    if (EPI == 1) {
        acc.x = fmaxf(acc.x, 0.0f); acc.y = fmaxf(acc.y, 0.0f);
        acc.z = fmaxf(acc.z, 0.0f); acc.w = fmaxf(acc.w, 0.0f);
    }

    uint2 o;
    *reinterpret_cast<__half2*>(&o.x) = __floats2half2_rn(acc.x, acc.y);
    *reinterpret_cast<__half2*>(&o.y) = __floats2half2_rn(acc.z, acc.w);
    ((uint2*)out)[(size_t)node * 32 + lane] = o;
}

// ---------------- launch ----------------

extern "C" void kernel_launch(void* const* d_in, const int* in_sizes, int n_in,
                              void* d_out, int out_size) {
    const float* x    = (const float*)d_in[0];
    const int*   ei   = (const int*)  d_in[1];
    const float* W1   = (const float*)d_in[2];
    const float* b1   = (const float*)d_in[3];
    const float* W2   = (const float*)d_in[4];
    const float* b2   = (const float*)d_in[5];
    const float* Wout = (const float*)d_in[6];
    const float* bout = (const float*)d_in[7];

    const int n = in_sizes[0] / D;
    const int E = in_sizes[1] / 2;
    const int* src = ei;
    const int* dst = ei + E;

    __half *h1, *h2, *agg1, *agg2;
    cudaGetSymbolAddress((void**)&h1,   g_h1);
    cudaGetSymbolAddress((void**)&agg1, g_agg1);
    cudaGetSymbolAddress((void**)&h2,   g_h2);
    cudaGetSymbolAddress((void**)&agg2, g_agg2);

    const bool vec_ok =
        ((((unsigned long long)src) | ((unsigned long long)dst)) & 15ull) == 0ull;

    // CSR build: degrees -> dinv + row offsets -> scatter (src only)
    zero_kernel<<<(n + 255) / 256, 256>>>(n);
    if (vec_ok) {
        int t4 = (E + 3) / 4;
        count_deg_kernel4<<<(t4 + 255) / 256, 256>>>(dst, E);
    } else {
        count_deg_kernel1<<<(E + 255) / 256, 256>>>(dst, E);
    }
    dinv_rowstart_kernel<<<(n + 255) / 256, 256>>>(n);
    if (vec_ok) {
        int t4 = (E + 3) / 4;
        scatter_kernel4<<<(t4 + 255) / 256, 256>>>(src, dst, E);
    } else {
        scatter_kernel1<<<(E + 255) / 256, 256>>>(src, dst, E);
    }

    const int gemm_blocks = (n + 63) / 64;
    const int agg_blocks  = (n + 7) / 8;

    // layer 1:  hw1 = (x @ W1) * dinv ; agg1 = relu(dinv*(S hw1) + b1)
    gemm128_kernel<true><<<gemm_blocks, 256>>>(x, W1, h1, n);
    agg_kernel<1><<<agg_blocks, 256>>>(h1, b1, agg1, n);

    // layer 2:  hw2 = (agg1 @ W2) * dinv ; agg2 = dinv*(S hw2) + b2
    gemm128_kernel<false><<<gemm_blocks, 256>>>(agg1, W2, h2, n);
    agg_kernel<2><<<agg_blocks, 256>>>(h2, b2, agg2, n);

    // output:  out = agg2 @ Wout + bout
    gemm_kernel<40, 5, true><<<gemm_blocks, 256>>>(agg2, Wout, bout, (float*)d_out, n);
}

// round 12
// speedup vs baseline: 4.4517x; 1.0864x over previous
#include <cuda_runtime.h>
#include <cuda_fp16.h>
#include <cuda_bf16.h>
#include <cstdint>

#define N_MAX 100000
#define E_MAX 1700000
#define D 128

// Scratch (device globals: no allocation allowed in kernel_launch)
__device__ __half g_xh[(size_t)N_MAX * D];    // fp16(x)
__device__ __half g_h1[(size_t)N_MAX * D];    // hw1 = (x@W1)*dinv[row]     (fp16)
__device__ __half g_agg1[(size_t)N_MAX * D];  // relu(dinv*S hw1 + b1)      (fp16)
__device__ __half g_h2[(size_t)N_MAX * D];    // hw2 = (agg1@W2)*dinv[row]  (fp16)
__device__ __half g_agg2[(size_t)N_MAX * D];  // dinv*S hw2 + b2            (fp16)
__device__ __half g_w1h[128 * 128];           // W1^T hi (fp16, [n][k])
__device__ __half g_w1l[128 * 128];           // W1^T lo
__device__ __half g_w2h[128 * 128];
__device__ __half g_w2l[128 * 128];
__device__ float  g_dinv[N_MAX];
__device__ int    g_deg[N_MAX];
__device__ int    g_fill[N_MAX];
__device__ int    g_rowptr[N_MAX];
__device__ int    g_ecnt;
__device__ int    g_esrc[E_MAX];              // CSR: src only (weights are algebraic)

// ---------------- helpers ----------------

__device__ __forceinline__ unsigned smem_u32(const void* p) {
    return (unsigned)__cvta_generic_to_shared(p);
}
__device__ __forceinline__ void cp_async16(unsigned dst, const void* src, int szbytes) {
    asm volatile("cp.async.cg.shared.global [%0], [%1], 16, %2;\n"
                 :: "r"(dst), "l"(src), "r"(szbytes));
}
__device__ __forceinline__ void cp_commit() {
    asm volatile("cp.async.commit_group;\n" ::);
}
__device__ __forceinline__ void cp_wait0() {
    asm volatile("cp.async.wait_group 0;\n" ::);
}
// fp16 MMA: D(16x8,f32) += A(16x16,f16) * B(16x8,f16)
__device__ __forceinline__ void mma_f16(float& c0, float& c1, float& c2, float& c3,
                                        unsigned a0, unsigned a1, unsigned a2, unsigned a3,
                                        unsigned b0, unsigned b1) {
    asm volatile("mma.sync.aligned.m16n8k16.row.col.f32.f16.f16.f32 "
                 "{%0,%1,%2,%3}, {%4,%5,%6,%7}, {%8,%9}, {%0,%1,%2,%3};\n"
                 : "+f"(c0), "+f"(c1), "+f"(c2), "+f"(c3)
                 : "r"(a0), "r"(a1), "r"(a2), "r"(a3), "r"(b0), "r"(b1));
}

// ---------------- prep: x -> fp16, W -> transposed fp16 hi/lo ----------------

__global__ void prep_x_kernel(const float* __restrict__ x,
                              __half* __restrict__ xh, long total4) {
    long i = (long)blockIdx.x * 256 + threadIdx.x;
    if (i >= total4) return;
    float4 v = ((const float4*)x)[i];
    __half2 h0 = __floats2half2_rn(v.x, v.y);
    __half2 h1 = __floats2half2_rn(v.z, v.w);
    ((__half2*)xh)[i * 2]     = h0;
    ((__half2*)xh)[i * 2 + 1] = h1;
}

__global__ void prep_w_kernel(const float* __restrict__ W,
                              __half* __restrict__ Wth, __half* __restrict__ Wtl) {
    int i = blockIdx.x * 256 + threadIdx.x;   // 16384 elems
    int k = i >> 7, nn = i & 127;
    float w = W[k * 128 + nn];
    __half h = __float2half_rn(w);
    float r = w - __half2float(h);
    Wth[nn * 128 + k] = h;
    Wtl[nn * 128 + k] = __float2half_rn(r);
}

// ---------------- CSR build ----------------

__global__ void zero_kernel(int n) {
    int i = blockIdx.x * blockDim.x + threadIdx.x;
    if (i < n) { g_deg[i] = 0; g_fill[i] = 0; }
    if (i == 0) g_ecnt = 0;
}

__global__ void count_deg_kernel4(const int* __restrict__ dst, int E) {
    int i = blockIdx.x * blockDim.x + threadIdx.x;
    int base = i * 4;
    if (base + 4 <= E) {
        int4 d4 = *(const int4*)(dst + base);
        atomicAdd(&g_deg[d4.x], 1);
        atomicAdd(&g_deg[d4.y], 1);
        atomicAdd(&g_deg[d4.z], 1);
        atomicAdd(&g_deg[d4.w], 1);
    } else {
        for (int e = base; e < E; e++) atomicAdd(&g_deg[dst[e]], 1);
    }
}
__global__ void count_deg_kernel1(const int* __restrict__ dst, int E) {
    int e = blockIdx.x * blockDim.x + threadIdx.x;
    if (e < E) atomicAdd(&g_deg[dst[e]], 1);
}

// dinv + CSR row offsets; block-aggregated bump (1 global atomic per 256 nodes)
__global__ void dinv_rowstart_kernel(int n) {
    __shared__ int wtot[8];
    __shared__ int base_sh;
    const int tid  = threadIdx.x;
    const int lane = tid & 31;
    const int wid  = tid >> 5;
    int i = blockIdx.x * 256 + tid;
    int d = (i < n) ? g_deg[i] : 0;

    int incl = d;
#pragma unroll
    for (int off = 1; off < 32; off <<= 1) {
        int t = __shfl_up_sync(0xFFFFFFFFu, incl, off);
        if (lane >= off) incl += t;
    }
    if (lane == 31) wtot[wid] = incl;
    __syncthreads();
    if (tid == 0) {
        int s = 0;
#pragma unroll
        for (int j = 0; j < 8; j++) { int t = wtot[j]; wtot[j] = s; s += t; }
        base_sh = atomicAdd(&g_ecnt, s);
    }
    __syncthreads();
    if (i < n) {
        g_dinv[i]   = rsqrtf((float)d + 1.0f);   // +1 self loop
        g_rowptr[i] = base_sh + wtot[wid] + (incl - d);
    }
}

__global__ void scatter_kernel4(const int* __restrict__ src,
                                const int* __restrict__ dst, int E) {
    int i = blockIdx.x * blockDim.x + threadIdx.x;
    int base = i * 4;
    if (base + 4 <= E) {
        int4 s4 = *(const int4*)(src + base);
        int4 d4 = *(const int4*)(dst + base);
        g_esrc[g_rowptr[d4.x] + atomicAdd(&g_fill[d4.x], 1)] = s4.x;
        g_esrc[g_rowptr[d4.y] + atomicAdd(&g_fill[d4.y], 1)] = s4.y;
        g_esrc[g_rowptr[d4.z] + atomicAdd(&g_fill[d4.z], 1)] = s4.z;
        g_esrc[g_rowptr[d4.w] + atomicAdd(&g_fill[d4.w], 1)] = s4.w;
    } else {
        for (int e = base; e < E; e++) {
            int s = src[e], d = dst[e];
            g_esrc[g_rowptr[d] + atomicAdd(&g_fill[d], 1)] = s;
        }
    }
}
__global__ void scatter_kernel1(const int* __restrict__ src,
                                const int* __restrict__ dst, int E) {
    int e = blockIdx.x * blockDim.x + threadIdx.x;
    if (e >= E) return;
    int s = src[e], d = dst[e];
    g_esrc[g_rowptr[d] + atomicAdd(&g_fill[d], 1)] = s;
}

// ---------------- GEMM 128x128: fp16 HMMA, split-fp16 weights ---------------
// out_h[row,:] = half( (in[row,:] @ (Wh + Wl)) * dinv[row] )
// A fp16 exact; W carried as hi+lo fp16 (=> ~21 mantissa bits on W).
// Dynamic smem tiles, KP=40 halfs (80B row stride, 16B-aligned cp.async dsts,
// conflict-free: word index stride/row = 20 -> g*20 mod 32 covers 8 groups x4).

constexpr int KP = 40;                       // padded k-stride (halfs)
constexpr int WTILE_H = 2 * 128 * KP;        // per hi/lo: 10240 halfs
constexpr int XTILE_H = 2 * 64 * KP;         // 5120 halfs
constexpr int GEMM_SMEM_BYTES = (2 * WTILE_H + XTILE_H) * 2;   // 51200 B

__global__ __launch_bounds__(256, 3)
void gemm128h_kernel(const __half* __restrict__ in,
                     const __half* __restrict__ Wth, const __half* __restrict__ Wtl,
                     __half* __restrict__ outh, int n) {
    extern __shared__ __half smem_dyn[];
    __half* wh = smem_dyn;                 // [2][128*KP]
    __half* wl = wh + WTILE_H;             // [2][128*KP]
    __half* xh = wl + WTILE_H;             // [2][64*KP]

    const int tid    = threadIdx.x;
    const int lane   = tid & 31;
    const int warp   = tid >> 5;
    const int warp_m = warp & 3;          // 4 warps over 64 rows (16 each)
    const int warp_n = warp >> 2;         // 2 warps over 128 cols (64 each)
    const int g      = lane >> 2;         // groupID 0..7
    const int tig    = lane & 3;          // thread-in-group 0..3
    const int row0   = blockIdx.x * 64;
    const int rbase  = warp_m * 16;
    const int nbase  = warp_n * 64;

    float acc[8][4];
#pragma unroll
    for (int i = 0; i < 8; i++)
#pragma unroll
        for (int j = 0; j < 4; j++) acc[i][j] = 0.0f;

    auto issue_tile = [&](int t) {
        const int k0  = t * 32;
        const int buf = t & 1;
        unsigned whd = smem_u32(wh + buf * 128 * KP);
        unsigned wld = smem_u32(wl + buf * 128 * KP);
        // W tiles: 128 rows x 32 halfs = 128 x 4 chunks of 16B
#pragma unroll
        for (int j = 0; j < 2; j++) {
            int u = tid + j * 256;               // [0,512)
            int r = u >> 2, c8 = u & 3;
            cp_async16(whd + (r * KP + c8 * 8) * 2, Wth + r * 128 + k0 + c8 * 8, 16);
            cp_async16(wld + (r * KP + c8 * 8) * 2, Wtl + r * 128 + k0 + c8 * 8, 16);
        }
        // X tile: 64 rows x 32 halfs = 256 chunks of 16B (1/thread)
        unsigned xd = smem_u32(xh + buf * 64 * KP);
        int r = tid >> 2, c8 = tid & 3;
        int row = row0 + r;
        int ok = (row < n);
        cp_async16(xd + (r * KP + c8 * 8) * 2,
                   in + (size_t)(ok ? row : 0) * 128 + k0 + c8 * 8, ok ? 16 : 0);
        cp_commit();
    };

    issue_tile(0);
    cp_wait0();
    __syncthreads();

    for (int t = 0; t < 4; t++) {
        if (t < 3) issue_tile(t + 1);
        const __half* whb = wh + (t & 1) * 128 * KP;
        const __half* wlb = wl + (t & 1) * 128 * KP;
        const __half* xb  = xh + (t & 1) * 64 * KP;
#pragma unroll
        for (int ks = 0; ks < 2; ks++) {
            const int kk0 = ks * 16;
            unsigned a0 = *(const unsigned*)&xb[(rbase + g)     * KP + kk0 + tig * 2];
            unsigned a1 = *(const unsigned*)&xb[(rbase + g + 8) * KP + kk0 + tig * 2];
            unsigned a2 = *(const unsigned*)&xb[(rbase + g)     * KP + kk0 + tig * 2 + 8];
            unsigned a3 = *(const unsigned*)&xb[(rbase + g + 8) * KP + kk0 + tig * 2 + 8];
#pragma unroll
            for (int nt = 0; nt < 8; nt++) {
                const int n0 = nbase + nt * 8;
                const __half* bhp = &whb[(n0 + g) * KP + kk0 + tig * 2];
                unsigned bh0 = *(const unsigned*)bhp;
                unsigned bh1 = *(const unsigned*)(bhp + 8);
                mma_f16(acc[nt][0], acc[nt][1], acc[nt][2], acc[nt][3],
                        a0, a1, a2, a3, bh0, bh1);
                const __half* blp = &wlb[(n0 + g) * KP + kk0 + tig * 2];
                unsigned bl0 = *(const unsigned*)blp;
                unsigned bl1 = *(const unsigned*)(blp + 8);
                mma_f16(acc[nt][0], acc[nt][1], acc[nt][2], acc[nt][3],
                        a0, a1, a2, a3, bl0, bl1);
            }
        }
        cp_wait0();
        __syncthreads();
    }

    const int rowA = row0 + rbase + g;
    const int rowB = rowA + 8;
    float dvA = (rowA < n) ? g_dinv[rowA] : 0.0f;
    float dvB = (rowB < n) ? g_dinv[rowB] : 0.0f;
#pragma unroll
    for (int nt = 0; nt < 8; nt++) {
        const int cn = nbase + nt * 8 + tig * 2;
        if (rowA < n)
            *(__half2*)(outh + (size_t)rowA * 128 + cn) =
                __floats2half2_rn(acc[nt][0] * dvA, acc[nt][1] * dvA);
        if (rowB < n)
            *(__half2*)(outh + (size_t)rowB * 128 + cn) =
                __floats2half2_rn(acc[nt][2] * dvB, acc[nt][3] * dvB);
    }
}

// ---------------- GEMM (NCOL=40): out = in(fp16) @ W + bout ----------------

template<int NCOL, int TN, bool OUTBIAS>
__global__ void gemm_kernel(const __half* __restrict__ in,
                            const float* __restrict__ W,
                            const float* __restrict__ bout,
                            float* __restrict__ out, int n) {
    constexpr int KT    = 32;
    constexpr int BROWS = 64;
    constexpr int CG    = NCOL / TN;
    constexpr int RG    = 256 / CG;
    constexpr int TM    = BROWS / RG;

    __shared__ float ws[KT][NCOL];
    __shared__ float xs[BROWS][KT];

    const int tid  = threadIdx.x;
    const int tcol = tid % CG;
    const int trow = tid / CG;
    const int row0 = blockIdx.x * BROWS;

    float acc[TM][TN];
#pragma unroll
    for (int i = 0; i < TM; i++)
#pragma unroll
        for (int j = 0; j < TN; j++) acc[i][j] = 0.0f;

    for (int k0 = 0; k0 < 128; k0 += KT) {
        for (int i = tid; i < KT * NCOL; i += 256) {
            int kk = i / NCOL, c = i % NCOL;
            ws[kk][c] = W[(size_t)(k0 + kk) * NCOL + c];
        }
        // X tile: fp16 -> fp32, vectorized 8-half chunks
        for (int i = tid; i < BROWS * (KT / 8); i += 256) {
            int r = i / (KT / 8), c8 = i % (KT / 8);
            int row = row0 + r;
            float4 packed = (row < n)
                ? *(const float4*)(in + (size_t)row * 128 + k0 + c8 * 8)
                : make_float4(0.f, 0.f, 0.f, 0.f);
            const __half2* hp = (const __half2*)&packed;
#pragma unroll
            for (int j = 0; j < 4; j++) {
                float2 f = (row < n) ? __half22float2(hp[j]) : make_float2(0.f, 0.f);
                xs[r][c8 * 8 + j * 2]     = f.x;
                xs[r][c8 * 8 + j * 2 + 1] = f.y;
            }
        }
        __syncthreads();

#pragma unroll
        for (int kk = 0; kk < KT; kk++) {
            float wv[TN], xv[TM];
#pragma unroll
            for (int j = 0; j < TN; j++) wv[j] = ws[kk][tcol * TN + j];
#pragma unroll
            for (int i = 0; i < TM; i++) xv[i] = xs[trow * TM + i][kk];
#pragma unroll
            for (int i = 0; i < TM; i++)
#pragma unroll
                for (int j = 0; j < TN; j++) acc[i][j] += xv[i] * wv[j];
        }
        __syncthreads();
    }

#pragma unroll
    for (int i = 0; i < TM; i++) {
        int row = row0 + trow * TM + i;
        if (row < n) {
#pragma unroll
            for (int j = 0; j < TN; j++) {
                float v = acc[i][j];
                if (OUTBIAS) v += bout[tcol * TN + j];
                out[(size_t)row * NCOL + tcol * TN + j] = v;
            }
        }
    }
}

// ---------------- aggregation: one warp per node, fp16 gather/out -----------
// in:  hw (fp16) = h * dinv[row]
// out[node] (fp16) = EPI( dinv[node] * (hw[node] + sum_e hw[src_e]) + bin )
// EPI: 1 = relu(v + bin), 2 = v + bin

__device__ __forceinline__ void acc_row(float4& acc, const uint2* hb,
                                        size_t node, int lane) {
    uint2 u = __ldg(&hb[node * 32 + lane]);
    float2 f0 = __half22float2(*reinterpret_cast<const __half2*>(&u.x));
    float2 f1 = __half22float2(*reinterpret_cast<const __half2*>(&u.y));
    acc.x += f0.x; acc.y += f0.y; acc.z += f1.x; acc.w += f1.y;
}

template<int EPI>
__global__ void agg_kernel(const __half* __restrict__ hw,
                           const float* __restrict__ bin,
                           __half* __restrict__ out, int n) {
    int warp = (blockIdx.x * blockDim.x + threadIdx.x) >> 5;
    if (warp >= n) return;
    const int node = warp;
    const int lane = threadIdx.x & 31;

    const uint2* hb = (const uint2*)hw;   // 32 x 8B per 128-half row
    float4 acc = make_float4(0.f, 0.f, 0.f, 0.f);
    acc_row(acc, hb, (size_t)node, lane);          // self (hw includes dinv[node])

    int e   = g_rowptr[node];
    int end = e + g_deg[node];

    for (; e + 4 <= end; e += 4) {
        int s0 = g_esrc[e + 0];
        int s1 = g_esrc[e + 1];
        int s2 = g_esrc[e + 2];
        int s3 = g_esrc[e + 3];
        acc_row(acc, hb, (size_t)s0, lane);
        acc_row(acc, hb, (size_t)s1, lane);
        acc_row(acc, hb, (size_t)s2, lane);
        acc_row(acc, hb, (size_t)s3, lane);
    }
    for (; e < end; e++)
        acc_row(acc, hb, (size_t)g_esrc[e], lane);

    float dv = g_dinv[node];
    float4 bb = ((const float4*)bin)[lane];
    acc.x = acc.x * dv + bb.x;
    acc.y = acc.y * dv + bb.y;
    acc.z = acc.z * dv + bb.z;
    acc.w = acc.w * dv + bb.w;
    if (EPI == 1) {
        acc.x = fmaxf(acc.x, 0.0f); acc.y = fmaxf(acc.y, 0.0f);
        acc.z = fmaxf(acc.z, 0.0f); acc.w = fmaxf(acc.w, 0.0f);
    }

    uint2 o;
    *reinterpret_cast<__half2*>(&o.x) = __floats2half2_rn(acc.x, acc.y);
    *reinterpret_cast<__half2*>(&o.y) = __floats2half2_rn(acc.z, acc.w);
    ((uint2*)out)[(size_t)node * 32 + lane] = o;
}

// ---------------- launch ----------------

extern "C" void kernel_launch(void* const* d_in, const int* in_sizes, int n_in,
                              void* d_out, int out_size) {
    const float* x    = (const float*)d_in[0];
    const int*   ei   = (const int*)  d_in[1];
    const float* W1   = (const float*)d_in[2];
    const float* b1   = (const float*)d_in[3];
    const float* W2   = (const float*)d_in[4];
    const float* b2   = (const float*)d_in[5];
    const float* Wout = (const float*)d_in[6];
    const float* bout = (const float*)d_in[7];

    const int n = in_sizes[0] / D;
    const int E = in_sizes[1] / 2;
    const int* src = ei;
    const int* dst = ei + E;

    __half *xh, *h1, *h2, *agg1, *agg2, *w1h, *w1l, *w2h, *w2l;
    cudaGetSymbolAddress((void**)&xh,   g_xh);
    cudaGetSymbolAddress((void**)&h1,   g_h1);
    cudaGetSymbolAddress((void**)&agg1, g_agg1);
    cudaGetSymbolAddress((void**)&h2,   g_h2);
    cudaGetSymbolAddress((void**)&agg2, g_agg2);
    cudaGetSymbolAddress((void**)&w1h,  g_w1h);
    cudaGetSymbolAddress((void**)&w1l,  g_w1l);
    cudaGetSymbolAddress((void**)&w2h,  g_w2h);
    cudaGetSymbolAddress((void**)&w2l,  g_w2l);

    cudaFuncSetAttribute(gemm128h_kernel,
                         cudaFuncAttributeMaxDynamicSharedMemorySize,
                         GEMM_SMEM_BYTES);

    const bool vec_ok =
        ((((unsigned long long)src) | ((unsigned long long)dst)) & 15ull) == 0ull;

    // prep: x -> fp16, W1/W2 -> transposed split-fp16
    {
        long total4 = (long)n * (D / 4);
        prep_x_kernel<<<(int)((total4 + 255) / 256), 256>>>(x, xh, total4);
        prep_w_kernel<<<64, 256>>>(W1, w1h, w1l);
        prep_w_kernel<<<64, 256>>>(W2, w2h, w2l);
    }

    // CSR build: degrees -> dinv + row offsets -> scatter (src only)
    zero_kernel<<<(n + 255) / 256, 256>>>(n);
    if (vec_ok) {
        int t4 = (E + 3) / 4;
        count_deg_kernel4<<<(t4 + 255) / 256, 256>>>(dst, E);
    } else {
        count_deg_kernel1<<<(E + 255) / 256, 256>>>(dst, E);
    }
    dinv_rowstart_kernel<<<(n + 255) / 256, 256>>>(n);
    if (vec_ok) {
        int t4 = (E + 3) / 4;
        scatter_kernel4<<<(t4 + 255) / 256, 256>>>(src, dst, E);
    } else {
        scatter_kernel1<<<(E + 255) / 256, 256>>>(src, dst, E);
    }

    const int gemm_blocks = (n + 63) / 64;
    const int agg_blocks  = (n + 7) / 8;

    // layer 1:  hw1 = (x @ W1) * dinv ; agg1 = relu(dinv*(S hw1) + b1)
    gemm128h_kernel<<<gemm_blocks, 256, GEMM_SMEM_BYTES>>>(xh, w1h, w1l, h1, n);
    agg_kernel<1><<<agg_blocks, 256>>>(h1, b1, agg1, n);

    // layer 2:  hw2 = (agg1 @ W2) * dinv ; agg2 = dinv*(S hw2) + b2
    gemm128h_kernel<<<gemm_blocks, 256, GEMM_SMEM_BYTES>>>(agg1, w2h, w2l, h2, n);
    agg_kernel<2><<<agg_blocks, 256>>>(h2, b2, agg2, n);

    // output:  out = agg2 @ Wout + bout
    gemm_kernel<40, 5, true><<<gemm_blocks, 256>>>(agg2, Wout, bout, (float*)d_out, n);
}

// round 13
// speedup vs baseline: 5.3887x; 1.2105x over previous
#include <cuda_runtime.h>
#include <cuda_fp16.h>
#include <cuda_bf16.h>
#include <cstdint>

#define N_MAX 100000
#define E_MAX 1700000
#define D 128

// Scratch (device globals: no allocation allowed in kernel_launch)
__device__ __half g_h1[(size_t)N_MAX * D];    // hw1 = (x@W1)*dinv[row]     (fp16)
__device__ __half g_agg1[(size_t)N_MAX * D];  // relu(dinv*S hw1 + b1)      (fp16)
__device__ __half g_h2[(size_t)N_MAX * D];    // hw2 = (agg1@W2)*dinv[row]  (fp16)
__device__ __half g_agg2[(size_t)N_MAX * D];  // dinv*S hw2 + b2            (fp16)
__device__ __half g_w1h[128 * 128];           // W1^T hi (fp16, [n][k])
__device__ __half g_w1l[128 * 128];           // W1^T lo
__device__ __half g_w2h[128 * 128];
__device__ __half g_w2l[128 * 128];
__device__ __half g_woh[64 * 128];            // Wout^T hi, padded 40->64 rows
__device__ __half g_wol[64 * 128];
__device__ float  g_dinv[N_MAX];
__device__ int    g_deg[N_MAX];
__device__ int    g_fill[N_MAX];
__device__ int    g_rowptr[N_MAX];
__device__ int    g_ecnt;
__device__ int    g_esrc[E_MAX];              // CSR: src only (weights are algebraic)

// ---------------- helpers ----------------

__device__ __forceinline__ unsigned smem_u32(const void* p) {
    return (unsigned)__cvta_generic_to_shared(p);
}
__device__ __forceinline__ void cp_async16(unsigned dst, const void* src, int szbytes) {
    asm volatile("cp.async.cg.shared.global [%0], [%1], 16, %2;\n"
                 :: "r"(dst), "l"(src), "r"(szbytes));
}
__device__ __forceinline__ void cp_commit() {
    asm volatile("cp.async.commit_group;\n" ::);
}
__device__ __forceinline__ void cp_wait0() {
    asm volatile("cp.async.wait_group 0;\n" ::);
}
__device__ __forceinline__ unsigned packh2(float f0, float f1) {
    __half2 h = __floats2half2_rn(f0, f1);
    return *reinterpret_cast<unsigned*>(&h);
}
// fp16 MMA: D(16x8,f32) += A(16x16,f16) * B(16x8,f16)
__device__ __forceinline__ void mma_f16(float& c0, float& c1, float& c2, float& c3,
                                        unsigned a0, unsigned a1, unsigned a2, unsigned a3,
                                        unsigned b0, unsigned b1) {
    asm volatile("mma.sync.aligned.m16n8k16.row.col.f32.f16.f16.f32 "
                 "{%0,%1,%2,%3}, {%4,%5,%6,%7}, {%8,%9}, {%0,%1,%2,%3};\n"
                 : "+f"(c0), "+f"(c1), "+f"(c2), "+f"(c3)
                 : "r"(a0), "r"(a1), "r"(a2), "r"(a3), "r"(b0), "r"(b1));
}

// ---------------- prep: W -> transposed fp16 hi/lo ----------------

__global__ void prep_w_kernel(const float* __restrict__ W,
                              __half* __restrict__ Wth, __half* __restrict__ Wtl) {
    int i = blockIdx.x * 256 + threadIdx.x;   // 16384 elems
    int k = i >> 7, nn = i & 127;
    float w = W[k * 128 + nn];
    __half h = __float2half_rn(w);
    float r = w - __half2float(h);
    Wth[nn * 128 + k] = h;
    Wtl[nn * 128 + k] = __float2half_rn(r);
}

// Wout [128 x 40] -> padded transposed [64][128] hi/lo
__global__ void prep_wout_kernel(const float* __restrict__ W,
                                 __half* __restrict__ Wth, __half* __restrict__ Wtl) {
    int i = blockIdx.x * 256 + threadIdx.x;   // 64*128 = 8192 elems
    if (i >= 64 * 128) return;
    int nn = i >> 7, k = i & 127;
    float w = (nn < 40) ? W[k * 40 + nn] : 0.0f;
    __half h = __float2half_rn(w);
    float r = w - __half2float(h);
    Wth[nn * 128 + k] = h;
    Wtl[nn * 128 + k] = __float2half_rn(r);
}

// ---------------- CSR build ----------------

__global__ void zero_kernel(int n) {
    int i = blockIdx.x * blockDim.x + threadIdx.x;
    if (i < n) { g_deg[i] = 0; g_fill[i] = 0; }
    if (i == 0) g_ecnt = 0;
}

__global__ void count_deg_kernel4(const int* __restrict__ dst, int E) {
    int i = blockIdx.x * blockDim.x + threadIdx.x;
    int base = i * 4;
    if (base + 4 <= E) {
        int4 d4 = *(const int4*)(dst + base);
        atomicAdd(&g_deg[d4.x], 1);
        atomicAdd(&g_deg[d4.y], 1);
        atomicAdd(&g_deg[d4.z], 1);
        atomicAdd(&g_deg[d4.w], 1);
    } else {
        for (int e = base; e < E; e++) atomicAdd(&g_deg[dst[e]], 1);
    }
}
__global__ void count_deg_kernel1(const int* __restrict__ dst, int E) {
    int e = blockIdx.x * blockDim.x + threadIdx.x;
    if (e < E) atomicAdd(&g_deg[dst[e]], 1);
}

// dinv + CSR row offsets; block-aggregated bump (1 global atomic per 256 nodes)
__global__ void dinv_rowstart_kernel(int n) {
    __shared__ int wtot[8];
    __shared__ int base_sh;
    const int tid  = threadIdx.x;
    const int lane = tid & 31;
    const int wid  = tid >> 5;
    int i = blockIdx.x * 256 + tid;
    int d = (i < n) ? g_deg[i] : 0;

    int incl = d;
#pragma unroll
    for (int off = 1; off < 32; off <<= 1) {
        int t = __shfl_up_sync(0xFFFFFFFFu, incl, off);
        if (lane >= off) incl += t;
    }
    if (lane == 31) wtot[wid] = incl;
    __syncthreads();
    if (tid == 0) {
        int s = 0;
#pragma unroll
        for (int j = 0; j < 8; j++) { int t = wtot[j]; wtot[j] = s; s += t; }
        base_sh = atomicAdd(&g_ecnt, s);
    }
    __syncthreads();
    if (i < n) {
        g_dinv[i]   = rsqrtf((float)d + 1.0f);   // +1 self loop
        g_rowptr[i] = base_sh + wtot[wid] + (incl - d);
    }
}

__global__ void scatter_kernel4(const int* __restrict__ src,
                                const int* __restrict__ dst, int E) {
    int i = blockIdx.x * blockDim.x + threadIdx.x;
    int base = i * 4;
    if (base + 4 <= E) {
        int4 s4 = *(const int4*)(src + base);
        int4 d4 = *(const int4*)(dst + base);
        g_esrc[g_rowptr[d4.x] + atomicAdd(&g_fill[d4.x], 1)] = s4.x;
        g_esrc[g_rowptr[d4.y] + atomicAdd(&g_fill[d4.y], 1)] = s4.y;
        g_esrc[g_rowptr[d4.z] + atomicAdd(&g_fill[d4.z], 1)] = s4.z;
        g_esrc[g_rowptr[d4.w] + atomicAdd(&g_fill[d4.w], 1)] = s4.w;
    } else {
        for (int e = base; e < E; e++) {
            int s = src[e], d = dst[e];
            g_esrc[g_rowptr[d] + atomicAdd(&g_fill[d], 1)] = s;
        }
    }
}
__global__ void scatter_kernel1(const int* __restrict__ src,
                                const int* __restrict__ dst, int E) {
    int e = blockIdx.x * blockDim.x + threadIdx.x;
    if (e >= E) return;
    int s = src[e], d = dst[e];
    g_esrc[g_rowptr[d] + atomicAdd(&g_fill[d], 1)] = s;
}

// ---------------- GEMM 128x128: fp16 HMMA, split-fp16 weights ---------------
// out_h[row,:] = half( (in[row,:] @ (Wh + Wl)) * dinv[row] )
// XFP32: X tile loaded fp32, converted to fp16 at frag build (layer 1, no prep
// pass). Else X already fp16 (exact in tf32/fp16).

constexpr int KP  = 40;                      // padded k-stride (halfs)
constexpr int XPF = 36;                      // padded k-stride (floats) for fp32 X
constexpr int WTILE_H = 2 * 128 * KP;        // per hi/lo, dbl-buffered: 10240 halfs
constexpr int XTILE_H = 2 * 64 * KP;         // 5120 halfs
constexpr int XTILE_F = 2 * 64 * XPF;        // 4608 floats
constexpr int GEMM_SMEM_F16X = (2 * WTILE_H + XTILE_H) * 2;        // 51200 B
constexpr int GEMM_SMEM_F32X = (2 * WTILE_H) * 2 + XTILE_F * 4;    // 59392 B

template<bool XFP32>
__global__ __launch_bounds__(256, 3)
void gemm128h_kernel(const void* __restrict__ in_,
                     const __half* __restrict__ Wth, const __half* __restrict__ Wtl,
                     __half* __restrict__ outh, int n) {
    extern __shared__ __half smem_dyn[];
    __half* wh = smem_dyn;                 // [2][128*KP]
    __half* wl = wh + WTILE_H;             // [2][128*KP]
    __half* xh = wl + WTILE_H;             // fp16 X  [2][64*KP]
    float*  xf = (float*)(wl + WTILE_H);   // fp32 X  [2][64*XPF] (16B aligned)

    const int tid    = threadIdx.x;
    const int lane   = tid & 31;
    const int warp   = tid >> 5;
    const int warp_m = warp & 3;          // 4 warps over 64 rows (16 each)
    const int warp_n = warp >> 2;         // 2 warps over 128 cols (64 each)
    const int g      = lane >> 2;         // groupID 0..7
    const int tig    = lane & 3;          // thread-in-group 0..3
    const int row0   = blockIdx.x * 64;
    const int rbase  = warp_m * 16;
    const int nbase  = warp_n * 64;

    float acc[8][4];
#pragma unroll
    for (int i = 0; i < 8; i++)
#pragma unroll
        for (int j = 0; j < 4; j++) acc[i][j] = 0.0f;

    auto issue_tile = [&](int t) {
        const int k0  = t * 32;
        const int buf = t & 1;
        unsigned whd = smem_u32(wh + buf * 128 * KP);
        unsigned wld = smem_u32(wl + buf * 128 * KP);
        // W tiles: 128 rows x 32 halfs = 128 x 4 chunks of 16B
#pragma unroll
        for (int j = 0; j < 2; j++) {
            int u = tid + j * 256;               // [0,512)
            int r = u >> 2, c8 = u & 3;
            cp_async16(whd + (r * KP + c8 * 8) * 2, Wth + r * 128 + k0 + c8 * 8, 16);
            cp_async16(wld + (r * KP + c8 * 8) * 2, Wtl + r * 128 + k0 + c8 * 8, 16);
        }
        if (XFP32) {
            const float* in = (const float*)in_;
            unsigned xd = smem_u32(xf + buf * 64 * XPF);
            // 64 rows x 32 floats = 512 chunks of 16B (2/thread)
#pragma unroll
            for (int j = 0; j < 2; j++) {
                int u = tid + j * 256;
                int r = u >> 3, c4 = u & 7;
                int row = row0 + r;
                int ok = (row < n);
                cp_async16(xd + (r * XPF + c4 * 4) * 4,
                           in + (size_t)(ok ? row : 0) * 128 + k0 + c4 * 4, ok ? 16 : 0);
            }
        } else {
            const __half* in = (const __half*)in_;
            unsigned xd = smem_u32(xh + buf * 64 * KP);
            // 64 rows x 32 halfs = 256 chunks of 16B (1/thread)
            int r = tid >> 2, c8 = tid & 3;
            int row = row0 + r;
            int ok = (row < n);
            cp_async16(xd + (r * KP + c8 * 8) * 2,
                       in + (size_t)(ok ? row : 0) * 128 + k0 + c8 * 8, ok ? 16 : 0);
        }
        cp_commit();
    };

    issue_tile(0);
    cp_wait0();
    __syncthreads();

    for (int t = 0; t < 4; t++) {
        if (t < 3) issue_tile(t + 1);
        const __half* whb = wh + (t & 1) * 128 * KP;
        const __half* wlb = wl + (t & 1) * 128 * KP;
        const __half* xb  = xh + (t & 1) * 64 * KP;
        const float*  xfb = xf + (t & 1) * 64 * XPF;
#pragma unroll
        for (int ks = 0; ks < 2; ks++) {
            const int kk0 = ks * 16;
            unsigned a0, a1, a2, a3;
            if (XFP32) {
                const float* x0 = xfb + (rbase + g)     * XPF + kk0 + tig * 2;
                const float* x1 = xfb + (rbase + g + 8) * XPF + kk0 + tig * 2;
                a0 = packh2(x0[0], x0[1]);
                a1 = packh2(x1[0], x1[1]);
                a2 = packh2(x0[8], x0[9]);
                a3 = packh2(x1[8], x1[9]);
            } else {
                a0 = *(const unsigned*)&xb[(rbase + g)     * KP + kk0 + tig * 2];
                a1 = *(const unsigned*)&xb[(rbase + g + 8) * KP + kk0 + tig * 2];
                a2 = *(const unsigned*)&xb[(rbase + g)     * KP + kk0 + tig * 2 + 8];
                a3 = *(const unsigned*)&xb[(rbase + g + 8) * KP + kk0 + tig * 2 + 8];
            }
#pragma unroll
            for (int nt = 0; nt < 8; nt++) {
                const int n0 = nbase + nt * 8;
                const __half* bhp = &whb[(n0 + g) * KP + kk0 + tig * 2];
                unsigned bh0 = *(const unsigned*)bhp;
                unsigned bh1 = *(const unsigned*)(bhp + 8);
                mma_f16(acc[nt][0], acc[nt][1], acc[nt][2], acc[nt][3],
                        a0, a1, a2, a3, bh0, bh1);
                const __half* blp = &wlb[(n0 + g) * KP + kk0 + tig * 2];
                unsigned bl0 = *(const unsigned*)blp;
                unsigned bl1 = *(const unsigned*)(blp + 8);
                mma_f16(acc[nt][0], acc[nt][1], acc[nt][2], acc[nt][3],
                        a0, a1, a2, a3, bl0, bl1);
            }
        }
        cp_wait0();
        __syncthreads();
    }

    const int rowA = row0 + rbase + g;
    const int rowB = rowA + 8;
    float dvA = (rowA < n) ? g_dinv[rowA] : 0.0f;
    float dvB = (rowB < n) ? g_dinv[rowB] : 0.0f;
#pragma unroll
    for (int nt = 0; nt < 8; nt++) {
        const int cn = nbase + nt * 8 + tig * 2;
        if (rowA < n)
            *(__half2*)(outh + (size_t)rowA * 128 + cn) =
                __floats2half2_rn(acc[nt][0] * dvA, acc[nt][1] * dvA);
        if (rowB < n)
            *(__half2*)(outh + (size_t)rowB * 128 + cn) =
                __floats2half2_rn(acc[nt][2] * dvB, acc[nt][3] * dvB);
    }
}

// ---------------- GEMM 64-col (output layer): HMMA, fp32 out + bias ----------
// out[row, 0..39] = (in[row,:] @ (Wh + Wl))[0..39] + bout

__global__ void gemm64h_kernel(const __half* __restrict__ in,
                               const __half* __restrict__ Wth,
                               const __half* __restrict__ Wtl,
                               const float* __restrict__ bout,
                               float* __restrict__ out, int n) {
    __shared__ __half wh[2][64 * KP];
    __shared__ __half wl[2][64 * KP];
    __shared__ __half xs[2][64 * KP];

    const int tid    = threadIdx.x;
    const int lane   = tid & 31;
    const int warp   = tid >> 5;
    const int warp_m = warp & 3;          // 4 warps over 64 rows
    const int warp_n = warp >> 2;         // 2 warps over 64 cols (32 each)
    const int g      = lane >> 2;
    const int tig    = lane & 3;
    const int row0   = blockIdx.x * 64;
    const int rbase  = warp_m * 16;
    const int nbase  = warp_n * 32;

    float acc[4][4];
#pragma unroll
    for (int i = 0; i < 4; i++)
#pragma unroll
        for (int j = 0; j < 4; j++) acc[i][j] = 0.0f;

    auto issue_tile = [&](int t) {
        const int k0  = t * 32;
        const int buf = t & 1;
        unsigned whd = smem_u32(&wh[buf][0]);
        unsigned wld = smem_u32(&wl[buf][0]);
        // W tiles: 64 rows x 4 chunks = 256 chunks (1/thread each for hi, lo)
        {
            int r = tid >> 2, c8 = tid & 3;
            cp_async16(whd + (r * KP + c8 * 8) * 2, Wth + r * 128 + k0 + c8 * 8, 16);
            cp_async16(wld + (r * KP + c8 * 8) * 2, Wtl + r * 128 + k0 + c8 * 8, 16);
        }
        unsigned xd = smem_u32(&xs[buf][0]);
        {
            int r = tid >> 2, c8 = tid & 3;
            int row = row0 + r;
            int ok = (row < n);
            cp_async16(xd + (r * KP + c8 * 8) * 2,
                       in + (size_t)(ok ? row : 0) * 128 + k0 + c8 * 8, ok ? 16 : 0);
        }
        cp_commit();
    };

    issue_tile(0);
    cp_wait0();
    __syncthreads();

    for (int t = 0; t < 4; t++) {
        if (t < 3) issue_tile(t + 1);
        const __half* whb = wh[t & 1];
        const __half* wlb = wl[t & 1];
        const __half* xb  = xs[t & 1];
#pragma unroll
        for (int ks = 0; ks < 2; ks++) {
            const int kk0 = ks * 16;
            unsigned a0 = *(const unsigned*)&xb[(rbase + g)     * KP + kk0 + tig * 2];
            unsigned a1 = *(const unsigned*)&xb[(rbase + g + 8) * KP + kk0 + tig * 2];
            unsigned a2 = *(const unsigned*)&xb[(rbase + g)     * KP + kk0 + tig * 2 + 8];
            unsigned a3 = *(const unsigned*)&xb[(rbase + g + 8) * KP + kk0 + tig * 2 + 8];
#pragma unroll
            for (int nt = 0; nt < 4; nt++) {
                const int n0 = nbase + nt * 8;
                const __half* bhp = &whb[(n0 + g) * KP + kk0 + tig * 2];
                unsigned bh0 = *(const unsigned*)bhp;
                unsigned bh1 = *(const unsigned*)(bhp + 8);
                mma_f16(acc[nt][0], acc[nt][1], acc[nt][2], acc[nt][3],
                        a0, a1, a2, a3, bh0, bh1);
                const __half* blp = &wlb[(n0 + g) * KP + kk0 + tig * 2];
                unsigned bl0 = *(const unsigned*)blp;
                unsigned bl1 = *(const unsigned*)(blp + 8);
                mma_f16(acc[nt][0], acc[nt][1], acc[nt][2], acc[nt][3],
                        a0, a1, a2, a3, bl0, bl1);
            }
        }
        cp_wait0();
        __syncthreads();
    }

    const int rowA = row0 + rbase + g;
    const int rowB = rowA + 8;
#pragma unroll
    for (int nt = 0; nt < 4; nt++) {
        const int cn = nbase + nt * 8 + tig * 2;
        if (cn < 40) {
            float b0 = bout[cn], b1 = bout[cn + 1];
            if (rowA < n)
                *(float2*)(out + (size_t)rowA * 40 + cn) =
                    make_float2(acc[nt][0] + b0, acc[nt][1] + b1);
            if (rowB < n)
                *(float2*)(out + (size_t)rowB * 40 + cn) =
                    make_float2(acc[nt][2] + b0, acc[nt][3] + b1);
        }
    }
}

// ---------------- aggregation: one warp per node, fp16 gather/out -----------
// in:  hw (fp16) = h * dinv[row]
// out[node] (fp16) = EPI( dinv[node] * (hw[node] + sum_e hw[src_e]) + bin )
// EPI: 1 = relu(v + bin), 2 = v + bin

__device__ __forceinline__ void acc_row(float4& acc, const uint2* hb,
                                        size_t node, int lane) {
    uint2 u = __ldg(&hb[node * 32 + lane]);
    float2 f0 = __half22float2(*reinterpret_cast<const __half2*>(&u.x));
    float2 f1 = __half22float2(*reinterpret_cast<const __half2*>(&u.y));
    acc.x += f0.x; acc.y += f0.y; acc.z += f1.x; acc.w += f1.y;
}

template<int EPI>
__global__ void agg_kernel(const __half* __restrict__ hw,
                           const float* __restrict__ bin,
                           __half* __restrict__ out, int n) {
    int warp = (blockIdx.x * blockDim.x + threadIdx.x) >> 5;
    if (warp >= n) return;
    const int node = warp;
    const int lane = threadIdx.x & 31;

    const uint2* hb = (const uint2*)hw;   // 32 x 8B per 128-half row
    float4 acc = make_float4(0.f, 0.f, 0.f, 0.f);
    acc_row(acc, hb, (size_t)node, lane);          // self (hw includes dinv[node])

    int e   = g_rowptr[node];
    int end = e + g_deg[node];

    for (; e + 4 <= end; e += 4) {
        int s0 = g_esrc[e + 0];
        int s1 = g_esrc[e + 1];
        int s2 = g_esrc[e + 2];
        int s3 = g_esrc[e + 3];
        acc_row(acc, hb, (size_t)s0, lane);
        acc_row(acc, hb, (size_t)s1, lane);
        acc_row(acc, hb, (size_t)s2, lane);
        acc_row(acc, hb, (size_t)s3, lane);
    }
    for (; e < end; e++)
        acc_row(acc, hb, (size_t)g_esrc[e], lane);

    float dv = g_dinv[node];
    float4 bb = ((const float4*)bin)[lane];
    acc.x = acc.x * dv + bb.x;
    acc.y = acc.y * dv + bb.y;
    acc.z = acc.z * dv + bb.z;
    acc.w = acc.w * dv + bb.w;
    if (EPI == 1) {
        acc.x = fmaxf(acc.x, 0.0f); acc.y = fmaxf(acc.y, 0.0f);
        acc.z = fmaxf(acc.z, 0.0f); acc.w = fmaxf(acc.w, 0.0f);
    }

    uint2 o;
    *reinterpret_cast<__half2*>(&o.x) = __floats2half2_rn(acc.x, acc.y);
    *reinterpret_cast<__half2*>(&o.y) = __floats2half2_rn(acc.z, acc.w);
    ((uint2*)out)[(size_t)node * 32 + lane] = o;
}

// ---------------- launch ----------------

extern "C" void kernel_launch(void* const* d_in, const int* in_sizes, int n_in,
                              void* d_out, int out_size) {
    const float* x    = (const float*)d_in[0];
    const int*   ei   = (const int*)  d_in[1];
    const float* W1   = (const float*)d_in[2];
    const float* b1   = (const float*)d_in[3];
    const float* W2   = (const float*)d_in[4];
    const float* b2   = (const float*)d_in[5];
    const float* Wout = (const float*)d_in[6];
    const float* bout = (const float*)d_in[7];

    const int n = in_sizes[0] / D;
    const int E = in_sizes[1] / 2;
    const int* src = ei;
    const int* dst = ei + E;

    __half *h1, *h2, *agg1, *agg2, *w1h, *w1l, *w2h, *w2l, *woh, *wol;
    cudaGetSymbolAddress((void**)&h1,   g_h1);
    cudaGetSymbolAddress((void**)&agg1, g_agg1);
    cudaGetSymbolAddress((void**)&h2,   g_h2);
    cudaGetSymbolAddress((void**)&agg2, g_agg2);
    cudaGetSymbolAddress((void**)&w1h,  g_w1h);
    cudaGetSymbolAddress((void**)&w1l,  g_w1l);
    cudaGetSymbolAddress((void**)&w2h,  g_w2h);
    cudaGetSymbolAddress((void**)&w2l,  g_w2l);
    cudaGetSymbolAddress((void**)&woh,  g_woh);
    cudaGetSymbolAddress((void**)&wol,  g_wol);

    cudaFuncSetAttribute(gemm128h_kernel<true>,
                         cudaFuncAttributeMaxDynamicSharedMemorySize,
                         GEMM_SMEM_F32X);
    cudaFuncSetAttribute(gemm128h_kernel<false>,
                         cudaFuncAttributeMaxDynamicSharedMemorySize,
                         GEMM_SMEM_F16X);

    const bool vec_ok =
        ((((unsigned long long)src) | ((unsigned long long)dst)) & 15ull) == 0ull;

    // prep: W1/W2/Wout -> transposed split-fp16
    prep_w_kernel<<<64, 256>>>(W1, w1h, w1l);
    prep_w_kernel<<<64, 256>>>(W2, w2h, w2l);
    prep_wout_kernel<<<32, 256>>>(Wout, woh, wol);

    // CSR build: degrees -> dinv + row offsets -> scatter (src only)
    zero_kernel<<<(n + 255) / 256, 256>>>(n);
    if (vec_ok) {
        int t4 = (E + 3) / 4;
        count_deg_kernel4<<<(t4 + 255) / 256, 256>>>(dst, E);
    } else {
        count_deg_kernel1<<<(E + 255) / 256, 256>>>(dst, E);
    }
    dinv_rowstart_kernel<<<(n + 255) / 256, 256>>>(n);
    if (vec_ok) {
        int t4 = (E + 3) / 4;
        scatter_kernel4<<<(t4 + 255) / 256, 256>>>(src, dst, E);
    } else {
        scatter_kernel1<<<(E + 255) / 256, 256>>>(src, dst, E);
    }

    const int gemm_blocks = (n + 63) / 64;
    const int agg_blocks  = (n + 7) / 8;

    // layer 1:  hw1 = (x @ W1) * dinv ; agg1 = relu(dinv*(S hw1) + b1)
    gemm128h_kernel<true><<<gemm_blocks, 256, GEMM_SMEM_F32X>>>(x, w1h, w1l, h1, n);
    agg_kernel<1><<<agg_blocks, 256>>>(h1, b1, agg1, n);

    // layer 2:  hw2 = (agg1 @ W2) * dinv ; agg2 = dinv*(S hw2) + b2
    gemm128h_kernel<false><<<gemm_blocks, 256, GEMM_SMEM_F16X>>>(agg1, w2h, w2l, h2, n);
    agg_kernel<2><<<agg_blocks, 256>>>(h2, b2, agg2, n);

    // output:  out = agg2 @ Wout + bout   (padded 64-col HMMA)
    gemm64h_kernel<<<gemm_blocks, 256>>>(agg2, woh, wol, bout, (float*)d_out, n);
}